// round 4
// baseline (speedup 1.0000x reference)
#include <cuda_runtime.h>
#include <cstdint>

// ============================================================================
// HGCN (2-layer hyperbolic GCN), c = 1.
//
// R4 pipeline:
//   CSR build (deg hist -> scan -> fill)                  [once, reused 2x]
//   xt1 = fusedGEMM<0>(x,  W1, hb1)   (f32x2 FFMA2 GEMM + encode scale +
//                                      full kA epilogue -> xt directly)
//   h1, xn = gather_kC(xt1)           (CSR gather + expmap/proj/relu/log/exp)
//   xt2 = fusedGEMM<1>(h1, W2, hb2)
//   out = gather_kC(xt2)
// ============================================================================

#define BALL_MAXN 0.996f     // (1 - 4e-3)/sqrt(c)
#define EPSN      1e-15f
#define NODES_MAX 80000
#define E_MAX     1300000
#define DIM       64

__device__ float d_xt [NODES_MAX * DIM];
__device__ float d_h1 [NODES_MAX * DIM];
__device__ float d_xn [NODES_MAX];
__device__ float d_hb1[65];
__device__ float d_hb2[65];
__device__ int   d_deg[NODES_MAX];
__device__ int   d_off[NODES_MAX];
__device__ int   d_cur[NODES_MAX];
__device__ int   d_bsum[256];
__device__ int   d_bsumex[256];
__device__ int2  d_edata[E_MAX];

__device__ __forceinline__ float wsum(float v) {
#pragma unroll
    for (int o = 16; o; o >>= 1) v += __shfl_xor_sync(0xffffffffu, v, o);
    return v;
}

__device__ __forceinline__ float artanh_f(float x) {
    x = fminf(fmaxf(x, -1.0f + 1e-7f), 1.0f - 1e-7f);
    return 0.5f * logf((1.0f + x) / (1.0f - x));
}

// packed fp32x2 FMA (SASS FFMA2) — only reachable via PTX
#define FFMA2(c, a, b) \
    asm("fma.rn.f32x2 %0, %1, %2, %3;" : "=l"(c) : "l"(a), "l"(b), "l"(c))

__device__ __forceinline__ float2 unpack2(unsigned long long v) {
    float2 r;
    asm("mov.b64 {%0, %1}, %2;" : "=f"(r.x), "=f"(r.y) : "l"(v));
    return r;
}

// ---------------------------------------------------------------------------
// hb = proj(expmap0(b)); hb[64] = ||hb||^2.  One block, 64 threads.
// ---------------------------------------------------------------------------
__global__ void init_hb_kernel(const float* __restrict__ b, float* __restrict__ hb) {
    __shared__ float sm[2];
    int t = threadIdx.x;
    float v = b[t];
    float ss = wsum(v * v);
    if ((t & 31) == 0) sm[t >> 5] = ss;
    __syncthreads();
    float tot = sm[0] + sm[1];
    __syncthreads();
    float nr = sqrtf(tot);
    float n  = fmaxf(nr, EPSN);
    float tn = tanhf(n);
    float e  = v * (tn / n);
    float en = fmaxf(tn * (nr / n), EPSN);
    float cf = (en > BALL_MAXN) ? (BALL_MAXN / en) : 1.0f;
    e *= cf;
    hb[t] = e;
    float ss2 = wsum(e * e);
    if ((t & 31) == 0) sm[t >> 5] = ss2;
    __syncthreads();
    if (t == 0) hb[64] = sm[0] + sm[1];
}

// ---------------------------------------------------------------------------
// CSR build
// ---------------------------------------------------------------------------
__global__ void zero_deg_kernel(int* __restrict__ deg, int N) {
    int i = blockIdx.x * blockDim.x + threadIdx.x;
    if (i < N) deg[i] = 0;
}

__global__ void hist_kernel(const int* __restrict__ dst, int* __restrict__ deg, int E) {
    int e = blockIdx.x * blockDim.x + threadIdx.x;
    if (e < E) atomicAdd(&deg[dst[e]], 1);
}

__global__ void scan1_kernel(const int* __restrict__ deg, int* __restrict__ off,
                             int* __restrict__ bsum, int N) {
    __shared__ int sh[256];
    int tid  = threadIdx.x;
    int base = blockIdx.x * 1024;
    int idx0 = base + tid * 4;
    int v[4];
#pragma unroll
    for (int j = 0; j < 4; j++) {
        int id = idx0 + j;
        v[j] = (id < N) ? deg[id] : 0;
    }
    int t = v[0] + v[1] + v[2] + v[3];
    sh[tid] = t;
    __syncthreads();
#pragma unroll
    for (int o = 1; o < 256; o <<= 1) {
        int u = (tid >= o) ? sh[tid - o] : 0;
        __syncthreads();
        sh[tid] += u;
        __syncthreads();
    }
    int excl = sh[tid] - t;
    int run = excl;
#pragma unroll
    for (int j = 0; j < 4; j++) {
        int id = idx0 + j;
        if (id < N) off[id] = run;
        run += v[j];
    }
    if (tid == 255) bsum[blockIdx.x] = sh[255];
}

__global__ void scan2_kernel(const int* __restrict__ bsum, int* __restrict__ bsumex, int B) {
    __shared__ int sh[256];
    int tid = threadIdx.x;
    int t = (tid < B) ? bsum[tid] : 0;
    sh[tid] = t;
    __syncthreads();
#pragma unroll
    for (int o = 1; o < 256; o <<= 1) {
        int u = (tid >= o) ? sh[tid - o] : 0;
        __syncthreads();
        sh[tid] += u;
        __syncthreads();
    }
    if (tid < B) bsumex[tid] = sh[tid] - t;
}

__global__ void scan3_kernel(int* __restrict__ off, int* __restrict__ cur,
                             const int* __restrict__ bsumex, int N) {
    int i = blockIdx.x * blockDim.x + threadIdx.x;
    if (i < N) {
        int v = off[i] + bsumex[i >> 10];
        off[i] = v;
        cur[i] = v;
    }
}

__global__ void fill_kernel(const int* __restrict__ src, const int* __restrict__ dst,
                            const float* __restrict__ w, int* __restrict__ cur,
                            int2* __restrict__ ed, int E) {
    int e = blockIdx.x * blockDim.x + threadIdx.x;
    if (e >= E) return;
    int d = dst[e];
    int pos = atomicAdd(&cur[d], 1);
    ed[pos] = make_int2(src[e], __float_as_int(w[e]));
}

// ---------------------------------------------------------------------------
// Fused GEMM + kA:
//   mx = (MODE0 ? encode-scale(||x_row||) : 1) * (A_row @ W^T)
//   xt_row = A_r * mx_row + B_r * hb      (full kA chain collapsed to 2 scalars)
// Only two cross-thread reductions per row: ||mx||^2 and dot(mx, hb).
// BM=128, BN=64, BK=32, 256 threads, 8x4 tile via 16 FFMA2 / k-step.
// ---------------------------------------------------------------------------
#define BM 128
#define BN 64
#define BK 32

template <int MODE>
__global__ __launch_bounds__(256, 2)
void gemm_fused_kernel(const float* __restrict__ A, const float* __restrict__ W,
                       float* __restrict__ C, float* __restrict__ xn_io,
                       const float* __restrict__ hb, int N, int K) {
    __shared__ __align__(16) float As[BK][BM];   // k-major A tile (4096 floats)
    __shared__ __align__(16) float Wd[BK][BM];   // duplicated B tile {b,b} pairs
    __shared__ float hbs[65];

    float* sAs = &As[0][0];
    float* sWd = &Wd[0][0];

    int tid = threadIdx.x;
    int block_row = blockIdx.x * BM;
    int tr = tid >> 4;   // 0..15 -> rows tr*8 .. +7
    int tc = tid & 15;   // 0..15 -> cols tc*4 .. +3

    if (tid < 65) hbs[tid] = hb[tid];

    unsigned long long acc[4][4];   // [row-pair][col], each packs rows (2i,2i+1)
#pragma unroll
    for (int i = 0; i < 4; i++)
#pragma unroll
        for (int j = 0; j < 4; j++) acc[i][j] = 0ULL;
    float ssl[4] = {0.f, 0.f, 0.f, 0.f};

    for (int k0 = 0; k0 < K; k0 += BK) {
#pragma unroll
        for (int i = 0; i < 4; i++) {
            int idx = tid + i * 256;
            int r   = idx >> 3;
            int kq  = (idx & 7) << 2;
            int gr  = block_row + r;
            if (gr >= N) gr = N - 1;
            float4 v = *(const float4*)(A + (size_t)gr * K + k0 + kq);
            As[kq + 0][r] = v.x; As[kq + 1][r] = v.y;
            As[kq + 2][r] = v.z; As[kq + 3][r] = v.w;
            if (MODE == 0)
                ssl[i] += v.x * v.x + v.y * v.y + v.z * v.z + v.w * v.w;
        }
#pragma unroll
        for (int i = 0; i < 2; i++) {
            int idx = tid + i * 256;
            int c   = idx >> 3;
            int kq  = (idx & 7) << 2;
            float4 v = *(const float4*)(W + (size_t)c * K + k0 + kq);
            *(float2*)&Wd[kq + 0][c * 2] = make_float2(v.x, v.x);
            *(float2*)&Wd[kq + 1][c * 2] = make_float2(v.y, v.y);
            *(float2*)&Wd[kq + 2][c * 2] = make_float2(v.z, v.z);
            *(float2*)&Wd[kq + 3][c * 2] = make_float2(v.w, v.w);
        }
        __syncthreads();

#pragma unroll
        for (int kk = 0; kk < BK; kk++) {
            ulonglong2 a01 = *(const ulonglong2*)&As[kk][tr * 8];
            ulonglong2 a23 = *(const ulonglong2*)&As[kk][tr * 8 + 4];
            ulonglong2 b01 = *(const ulonglong2*)&Wd[kk][tc * 8];
            ulonglong2 b23 = *(const ulonglong2*)&Wd[kk][tc * 8 + 4];
            unsigned long long ap[4] = {a01.x, a01.y, a23.x, a23.y};
            unsigned long long bp[4] = {b01.x, b01.y, b23.x, b23.y};
#pragma unroll
            for (int i = 0; i < 4; i++)
#pragma unroll
                for (int j = 0; j < 4; j++)
                    FFMA2(acc[i][j], ap[i], bp[j]);
        }
        __syncthreads();
    }

    // ---- unpack accumulators ----
    float mx[8][4];
#pragma unroll
    for (int i = 0; i < 4; i++)
#pragma unroll
        for (int j = 0; j < 4; j++) {
            float2 u = unpack2(acc[i][j]);
            mx[2 * i    ][j] = u.x;
            mx[2 * i + 1][j] = u.y;
        }

    // ---- MODE 0: encode scale s(||x_row||) and xn ----
    if (MODE == 0) {
        sAs[0 * 256 + tid] = ssl[0]; sAs[1 * 256 + tid] = ssl[1];
        sAs[2 * 256 + tid] = ssl[2]; sAs[3 * 256 + tid] = ssl[3];
        __syncthreads();
        if (tid < 128) {
            int r   = tid;
            int grp = r >> 5;
            int t0  = (r & 31) << 3;
            float s2 = 0.0f;
#pragma unroll
            for (int j = 0; j < 8; j++) s2 += sAs[grp * 256 + t0 + j];
            float nxr = sqrtf(s2);
            float nx  = fmaxf(nxr, EPSN);
            float t   = tanhf(nx);
            float en  = fmaxf(t * (nxr / nx), EPSN);
            float cf  = (en > BALL_MAXN) ? (BALL_MAXN / en) : 1.0f;
            float sc  = (t / nx) * cf;
            float xnv = fmaxf(en * cf, EPSN);
            sAs[1024 + r] = sc;        // per-row encode scale
            sWd[2176 + r] = xnv;       // per-row xn (shared)
            int gr = block_row + r;
            if (gr < N) xn_io[gr] = xnv;
        }
        __syncthreads();
        float scv[8];
#pragma unroll
        for (int i = 0; i < 8; i++) scv[i] = sAs[1024 + tr * 8 + i];
        __syncthreads();
#pragma unroll
        for (int i = 0; i < 8; i++)
#pragma unroll
            for (int j = 0; j < 4; j++) mx[i][j] *= scv[i];
    }

    // ---- partials: s1 = ||mx||^2, s2 = dot(mx, hb)  (16 threads per row) ----
#pragma unroll
    for (int i = 0; i < 8; i++) {
        int r = tr * 8 + i;
        float p1 = 0.0f, p2 = 0.0f;
#pragma unroll
        for (int j = 0; j < 4; j++) {
            float m = mx[i][j];
            p1 += m * m;
            p2 += m * hbs[tc * 4 + j];
        }
        sAs[r * 17 + tc] = p1;
        sWd[r * 17 + tc] = p2;
    }
    __syncthreads();

    // ---- per-row scalar chain (kA math, reductions -> analytic) ----
    if (tid < 128) {
        int r  = tid;
        int gr = block_row + r;
        float mxn2 = 0.0f, mxy = 0.0f;
#pragma unroll
        for (int j = 0; j < 16; j++) {
            mxn2 += sAs[r * 17 + j];
            mxy  += sWd[r * 17 + j];
        }
        float xn;
        if (MODE == 0) xn = sWd[2176 + r];
        else           xn = xn_io[(gr < N) ? gr : (N - 1)];

        float mxnr = sqrtf(mxn2);
        float mxn  = fmaxf(mxnr, EPSN);
        float tv   = tanhf(mxn / xn * artanh_f(xn));
        float rs   = tv / mxn;
        float rn   = fmaxf(mxnr * fabsf(rs), EPSN);
        float f    = (rn > BALL_MAXN) ? (BALL_MAXN / rn) : 1.0f;
        float rsf  = rs * f;

        float y2  = hbs[64];
        float x2  = mxn2 * rsf * rsf;
        float xy  = mxy * rsf;
        float den = fmaxf(1.0f + 2.0f * xy + x2 * y2, EPSN);
        float ca  = (1.0f + 2.0f * xy + y2) / den;
        float cb  = (1.0f - x2) / den;

        float hn2 = ca * ca * x2 + 2.0f * ca * cb * xy + cb * cb * y2;
        float hnr = sqrtf(hn2);
        float hn  = fmaxf(hnr, EPSN);
        float cf2 = (hn > BALL_MAXN) ? (BALL_MAXN / hn) : 1.0f;
        float hna = fmaxf(hnr * cf2, EPSN);
        float lc  = artanh_f(hna) / hna;

        sWd[2304 + r] = lc * cf2 * ca * rsf;   // A_r (multiplies mx)
        sWd[2432 + r] = lc * cf2 * cb;         // B_r (multiplies hb)
    }
    __syncthreads();

    // ---- write xt = A*mx + B*hb ----
#pragma unroll
    for (int i = 0; i < 8; i++) {
        int r  = tr * 8 + i;
        int gr = block_row + r;
        if (gr >= N) continue;
        float Ar = sWd[2304 + r];
        float Br = sWd[2432 + r];
        float4 o = make_float4(Ar * mx[i][0] + Br * hbs[tc * 4 + 0],
                               Ar * mx[i][1] + Br * hbs[tc * 4 + 1],
                               Ar * mx[i][2] + Br * hbs[tc * 4 + 2],
                               Ar * mx[i][3] + Br * hbs[tc * 4 + 3]);
        *(float4*)(C + (size_t)gr * DIM + tc * 4) = o;
    }
}

// ---------------------------------------------------------------------------
// Gather + kC: agg = sum_e w*xt[src] over CSR list of this dst node, then
// h = proj(expmap0(agg)); xt = relu(logmap0(h)); out = proj(expmap0(xt)).
// Warp per node, 2 dims per lane.
// ---------------------------------------------------------------------------
__global__ void gather_kc_kernel(const float* __restrict__ xt,
                                 const int2* __restrict__ ed,
                                 const int* __restrict__ off,
                                 const int* __restrict__ deg,
                                 float* __restrict__ out,
                                 float* __restrict__ xn_out, int N) {
    int row  = blockIdx.x * 8 + (threadIdx.x >> 5);
    int lane = threadIdx.x & 31;
    if (row >= N) return;

    int beg = off[row];
    int dc  = deg[row];

    float ax = 0.0f, ay = 0.0f;
    for (int i0 = 0; i0 < dc; i0 += 32) {
        int i = i0 + lane;
        int2 e = (i < dc) ? __ldg(&ed[beg + i]) : make_int2(0, 0);
        int cnt = min(32, dc - i0);
        for (int j = 0; j < cnt; j++) {
            int   s  = __shfl_sync(0xffffffffu, e.x, j);
            float wt = __int_as_float(__shfl_sync(0xffffffffu, e.y, j));
            float2 v = *(const float2*)(xt + (size_t)s * DIM + lane * 2);
            ax = fmaf(wt, v.x, ax);
            ay = fmaf(wt, v.y, ay);
        }
    }

    float na2 = wsum(ax * ax + ay * ay);
    float nar = sqrtf(na2);
    float na  = fmaxf(nar, EPSN);
    float t   = tanhf(na);
    float f1  = t / na;
    float en  = fmaxf(t * (nar / na), EPSN);
    float c1  = (en > BALL_MAXN) ? (BALL_MAXN / en) : 1.0f;
    float hn  = fmaxf(en * c1, EPSN);
    float lco = artanh_f(hn) / hn * (f1 * c1);

    float lx = fmaxf(ax * lco, 0.0f);
    float ly = fmaxf(ay * lco, 0.0f);

    float nx2 = wsum(lx * lx + ly * ly);
    float nxr = sqrtf(nx2);
    float nx  = fmaxf(nxr, EPSN);
    float t2  = tanhf(nx);
    float f2  = t2 / nx;
    float en2 = fmaxf(t2 * (nxr / nx), EPSN);
    float c2  = (en2 > BALL_MAXN) ? (BALL_MAXN / en2) : 1.0f;

    float2 o = make_float2(lx * (f2 * c2), ly * (f2 * c2));
    *(float2*)(out + (size_t)row * DIM + lane * 2) = o;

    if (xn_out != nullptr && lane == 0)
        xn_out[row] = fmaxf(en2 * c2, EPSN);
}

// ---------------------------------------------------------------------------
// Launch
// ---------------------------------------------------------------------------
extern "C" void kernel_launch(void* const* d_in, const int* in_sizes, int n_in,
                              void* d_out, int out_size) {
    const float* x   = (const float*)d_in[0];
    const int*   src = (const int*)  d_in[1];
    const int*   dst = (const int*)  d_in[2];
    const float* ew  = (const float*)d_in[3];
    const float* W1  = (const float*)d_in[4];
    const float* b1  = (const float*)d_in[5];
    const float* W2  = (const float*)d_in[6];
    const float* b2  = (const float*)d_in[7];
    float* out = (float*)d_out;

    int N = in_sizes[0] / 256;
    int E = in_sizes[1];

    float *xt, *h1, *xn, *hb1, *hb2;
    int *deg, *off, *cur, *bsum, *bsumex;
    int2* edata;
    cudaGetSymbolAddress((void**)&xt,     d_xt);
    cudaGetSymbolAddress((void**)&h1,     d_h1);
    cudaGetSymbolAddress((void**)&xn,     d_xn);
    cudaGetSymbolAddress((void**)&hb1,    d_hb1);
    cudaGetSymbolAddress((void**)&hb2,    d_hb2);
    cudaGetSymbolAddress((void**)&deg,    d_deg);
    cudaGetSymbolAddress((void**)&off,    d_off);
    cudaGetSymbolAddress((void**)&cur,    d_cur);
    cudaGetSymbolAddress((void**)&bsum,   d_bsum);
    cudaGetSymbolAddress((void**)&bsumex, d_bsumex);
    cudaGetSymbolAddress((void**)&edata,  d_edata);

    int rowBlocks  = (N + 7) / 8;
    int gemmBlocks = (N + BM - 1) / BM;
    int nBlocks256 = (N + 255) / 256;
    int eBlocks256 = (E + 255) / 256;
    int scanBlocks = (N + 1023) / 1024;

    init_hb_kernel<<<1, 64>>>(b1, hb1);
    init_hb_kernel<<<1, 64>>>(b2, hb2);

    // ---- CSR build (shared by both layers) ----
    zero_deg_kernel<<<nBlocks256, 256>>>(deg, N);
    hist_kernel<<<eBlocks256, 256>>>(dst, deg, E);
    scan1_kernel<<<scanBlocks, 256>>>(deg, off, bsum, N);
    scan2_kernel<<<1, 256>>>(bsum, bsumex, scanBlocks);
    scan3_kernel<<<nBlocks256, 256>>>(off, cur, bsumex, N);
    fill_kernel<<<eBlocks256, 256>>>(src, dst, ew, cur, edata, E);

    // ---- layer 1 ----
    gemm_fused_kernel<0><<<gemmBlocks, 256>>>(x, W1, xt, xn, hb1, N, 256);
    gather_kc_kernel<<<rowBlocks, 256>>>(xt, edata, off, deg, h1, xn, N);

    // ---- layer 2 ----
    gemm_fused_kernel<1><<<gemmBlocks, 256>>>(h1, W2, xt, xn, hb2, N, 64);
    gather_kc_kernel<<<rowBlocks, 256>>>(xt, edata, off, deg, out, nullptr, N);
}

// round 7
// speedup vs baseline: 1.0395x; 1.0395x over previous
#include <cuda_runtime.h>
#include <cstdint>

// ============================================================================
// HGCN (2-layer hyperbolic GCN), c = 1.
//
// R5 pipeline:
//   CSR build (vectorized hist -> scan -> vectorized fill)   [once, reused 2x]
//   xt1 = fusedGEMM<0>(x,  W1, hb1)   (scalar-FFMA GEMM + encode scale +
//                                      kA epilogue via half-warp reductions)
//   h1, xn = gather_kC(xt1)
//   xt2 = fusedGEMM<1>(h1, W2, hb2)
//   out = gather_kC(xt2)
// ============================================================================

#define BALL_MAXN 0.996f     // (1 - 4e-3)/sqrt(c)
#define EPSN      1e-15f
#define NODES_MAX 80000
#define E_MAX     1300000
#define DIM       64

__device__ float d_xt [NODES_MAX * DIM];
__device__ float d_h1 [NODES_MAX * DIM];
__device__ float d_xn [NODES_MAX];
__device__ float d_hb1[65];
__device__ float d_hb2[65];
__device__ int   d_deg[NODES_MAX];
__device__ int   d_off[NODES_MAX];
__device__ int   d_cur[NODES_MAX];
__device__ int   d_bsum[256];
__device__ int   d_bsumex[256];
__device__ int2  d_edata[E_MAX];

__device__ __forceinline__ float wsum(float v) {
#pragma unroll
    for (int o = 16; o; o >>= 1) v += __shfl_xor_sync(0xffffffffu, v, o);
    return v;
}

__device__ __forceinline__ float hsum16(float v) {
#pragma unroll
    for (int o = 8; o; o >>= 1) v += __shfl_xor_sync(0xffffffffu, v, o);
    return v;
}

__device__ __forceinline__ float artanh_f(float x) {
    x = fminf(fmaxf(x, -1.0f + 1e-7f), 1.0f - 1e-7f);
    return 0.5f * logf((1.0f + x) / (1.0f - x));
}

// ---------------------------------------------------------------------------
// hb = proj(expmap0(b)); hb[64] = ||hb||^2.  One block, 64 threads.
// ---------------------------------------------------------------------------
__global__ void init_hb_kernel(const float* __restrict__ b, float* __restrict__ hb) {
    __shared__ float sm[2];
    int t = threadIdx.x;
    float v = b[t];
    float ss = wsum(v * v);
    if ((t & 31) == 0) sm[t >> 5] = ss;
    __syncthreads();
    float tot = sm[0] + sm[1];
    __syncthreads();
    float nr = sqrtf(tot);
    float n  = fmaxf(nr, EPSN);
    float tn = tanhf(n);
    float e  = v * (tn / n);
    float en = fmaxf(tn * (nr / n), EPSN);
    float cf = (en > BALL_MAXN) ? (BALL_MAXN / en) : 1.0f;
    e *= cf;
    hb[t] = e;
    float ss2 = wsum(e * e);
    if ((t & 31) == 0) sm[t >> 5] = ss2;
    __syncthreads();
    if (t == 0) hb[64] = sm[0] + sm[1];
}

// ---------------------------------------------------------------------------
// CSR build (hist + fill vectorized: 4 edges / thread for MLP)
// ---------------------------------------------------------------------------
__global__ void zero_deg_kernel(int* __restrict__ deg, int N) {
    int i = blockIdx.x * blockDim.x + threadIdx.x;
    if (i < N) deg[i] = 0;
}

__global__ void hist_kernel(const int* __restrict__ dst, int* __restrict__ deg, int E) {
    int i  = blockIdx.x * blockDim.x + threadIdx.x;
    int E4 = E >> 2;
    if (i < E4) {
        int4 d = __ldg((const int4*)dst + i);
        atomicAdd(&deg[d.x], 1);
        atomicAdd(&deg[d.y], 1);
        atomicAdd(&deg[d.z], 1);
        atomicAdd(&deg[d.w], 1);
    } else if (i == E4) {
        for (int e = E4 * 4; e < E; e++) atomicAdd(&deg[dst[e]], 1);
    }
}

__global__ void scan1_kernel(const int* __restrict__ deg, int* __restrict__ off,
                             int* __restrict__ bsum, int N) {
    __shared__ int sh[256];
    int tid  = threadIdx.x;
    int base = blockIdx.x * 1024;
    int idx0 = base + tid * 4;
    int v[4];
#pragma unroll
    for (int j = 0; j < 4; j++) {
        int id = idx0 + j;
        v[j] = (id < N) ? deg[id] : 0;
    }
    int t = v[0] + v[1] + v[2] + v[3];
    sh[tid] = t;
    __syncthreads();
#pragma unroll
    for (int o = 1; o < 256; o <<= 1) {
        int u = (tid >= o) ? sh[tid - o] : 0;
        __syncthreads();
        sh[tid] += u;
        __syncthreads();
    }
    int excl = sh[tid] - t;
    int run = excl;
#pragma unroll
    for (int j = 0; j < 4; j++) {
        int id = idx0 + j;
        if (id < N) off[id] = run;
        run += v[j];
    }
    if (tid == 255) bsum[blockIdx.x] = sh[255];
}

__global__ void scan2_kernel(const int* __restrict__ bsum, int* __restrict__ bsumex, int B) {
    __shared__ int sh[256];
    int tid = threadIdx.x;
    int t = (tid < B) ? bsum[tid] : 0;
    sh[tid] = t;
    __syncthreads();
#pragma unroll
    for (int o = 1; o < 256; o <<= 1) {
        int u = (tid >= o) ? sh[tid - o] : 0;
        __syncthreads();
        sh[tid] += u;
        __syncthreads();
    }
    if (tid < B) bsumex[tid] = sh[tid] - t;
}

__global__ void scan3_kernel(int* __restrict__ off, int* __restrict__ cur,
                             const int* __restrict__ bsumex, int N) {
    int i = blockIdx.x * blockDim.x + threadIdx.x;
    if (i < N) {
        int v = off[i] + bsumex[i >> 10];
        off[i] = v;
        cur[i] = v;
    }
}

__global__ void fill_kernel(const int* __restrict__ src, const int* __restrict__ dst,
                            const float* __restrict__ w, int* __restrict__ cur,
                            int2* __restrict__ ed, int E) {
    int i  = blockIdx.x * blockDim.x + threadIdx.x;
    int E4 = E >> 2;
    if (i < E4) {
        int4   s = __ldg((const int4*)src + i);
        int4   d = __ldg((const int4*)dst + i);
        float4 f = __ldg((const float4*)w + i);
        int p0 = atomicAdd(&cur[d.x], 1);
        int p1 = atomicAdd(&cur[d.y], 1);
        int p2 = atomicAdd(&cur[d.z], 1);
        int p3 = atomicAdd(&cur[d.w], 1);
        ed[p0] = make_int2(s.x, __float_as_int(f.x));
        ed[p1] = make_int2(s.y, __float_as_int(f.y));
        ed[p2] = make_int2(s.z, __float_as_int(f.z));
        ed[p3] = make_int2(s.w, __float_as_int(f.w));
    } else if (i == E4) {
        for (int e = E4 * 4; e < E; e++) {
            int p = atomicAdd(&cur[dst[e]], 1);
            ed[p] = make_int2(src[e], __float_as_int(w[e]));
        }
    }
}

// ---------------------------------------------------------------------------
// Fused GEMM + kA:
//   mx = (MODE0 ? encode-scale(||x_row||) : 1) * (A_row @ W^T)
//   xt_row = A_r * mx_row + B_r * hb   (kA chain collapsed to 2 scalars/row,
//   needing only ||mx||^2 and dot(mx,hb); each row's 16 owner threads form a
//   contiguous half-warp -> shfl reductions, no smem)
// BM=128, BN=64, BK=32, 256 threads, 8x4 scalar-FFMA register tile.
// ---------------------------------------------------------------------------
#define BM 128
#define BN 64
#define BK 32

template <int MODE>
__global__ __launch_bounds__(256, 2)
void gemm_fused_kernel(const float* __restrict__ A, const float* __restrict__ W,
                       float* __restrict__ C, float* __restrict__ xn_io,
                       const float* __restrict__ hb, int N, int K) {
    __shared__ __align__(16) float As[BK][BM];  // k-major
    __shared__ __align__(16) float Ws[BK][BN];
    __shared__ float hbs[65];

    float* sAs = &As[0][0];

    int tid = threadIdx.x;
    int block_row = blockIdx.x * BM;
    int tr = tid >> 4;   // 0..15 -> rows tr*8 .. +7
    int tc = tid & 15;   // 0..15 -> cols tc*4 .. +3

    if (tid < 65) hbs[tid] = hb[tid];

    float acc[8][4];
#pragma unroll
    for (int i = 0; i < 8; i++)
#pragma unroll
        for (int j = 0; j < 4; j++) acc[i][j] = 0.0f;
    float ssl[4] = {0.f, 0.f, 0.f, 0.f};

    for (int k0 = 0; k0 < K; k0 += BK) {
#pragma unroll
        for (int i = 0; i < 4; i++) {
            int idx = tid + i * 256;
            int r   = idx >> 3;
            int kq  = (idx & 7) << 2;
            int gr  = block_row + r;
            if (gr >= N) gr = N - 1;
            float4 v = *(const float4*)(A + (size_t)gr * K + k0 + kq);
            As[kq + 0][r] = v.x; As[kq + 1][r] = v.y;
            As[kq + 2][r] = v.z; As[kq + 3][r] = v.w;
            if (MODE == 0)
                ssl[i] += v.x * v.x + v.y * v.y + v.z * v.z + v.w * v.w;
        }
#pragma unroll
        for (int i = 0; i < 2; i++) {
            int idx = tid + i * 256;
            int c   = idx >> 3;
            int kq  = (idx & 7) << 2;
            float4 v = *(const float4*)(W + (size_t)c * K + k0 + kq);
            Ws[kq + 0][c] = v.x; Ws[kq + 1][c] = v.y;
            Ws[kq + 2][c] = v.z; Ws[kq + 3][c] = v.w;
        }
        __syncthreads();

#pragma unroll
        for (int kk = 0; kk < BK; kk++) {
            float4 a0 = *(const float4*)&As[kk][tr * 8];
            float4 a1 = *(const float4*)&As[kk][tr * 8 + 4];
            float4 b  = *(const float4*)&Ws[kk][tc * 4];
            float av[8] = {a0.x, a0.y, a0.z, a0.w, a1.x, a1.y, a1.z, a1.w};
            float bv[4] = {b.x, b.y, b.z, b.w};
#pragma unroll
            for (int i = 0; i < 8; i++)
#pragma unroll
                for (int j = 0; j < 4; j++)
                    acc[i][j] = fmaf(av[i], bv[j], acc[i][j]);
        }
        __syncthreads();
    }

    // ---- MODE 0: per-row encode scale s(||x_row||) and xn (smem reduce) ----
    float scv[8];
#pragma unroll
    for (int i = 0; i < 8; i++) scv[i] = 1.0f;

    if (MODE == 0) {
        sAs[tid] = ssl[0]; sAs[256 + tid] = ssl[1];
        sAs[512 + tid] = ssl[2]; sAs[768 + tid] = ssl[3];
        __syncthreads();
        if (tid < 128) {
            int r   = tid;
            int grp = r >> 5;
            int t0  = (r & 31) << 3;
            float s2 = 0.0f;
#pragma unroll
            for (int j = 0; j < 8; j++) s2 += sAs[grp * 256 + t0 + j];
            float nxr = sqrtf(s2);
            float nx  = fmaxf(nxr, EPSN);
            float t   = tanhf(nx);
            float en  = fmaxf(t * (nxr / nx), EPSN);
            float cf  = (en > BALL_MAXN) ? (BALL_MAXN / en) : 1.0f;
            float sc  = (t / nx) * cf;
            float xnv = fmaxf(en * cf, EPSN);
            sAs[1024 + r] = sc;
            sAs[1152 + r] = xnv;
            int gr = block_row + r;
            if (gr < N) xn_io[gr] = xnv;
        }
        __syncthreads();
#pragma unroll
        for (int i = 0; i < 8; i++) scv[i] = sAs[1024 + tr * 8 + i];
    }

    // ---- per-row kA epilogue: half-warp reductions + scalar chain ----
    float y2 = hbs[64];
#pragma unroll
    for (int i = 0; i < 8; i++) {
        int r  = tr * 8 + i;
        int gr = block_row + r;

        float m0 = acc[i][0] * scv[i];
        float m1 = acc[i][1] * scv[i];
        float m2 = acc[i][2] * scv[i];
        float m3 = acc[i][3] * scv[i];
        float h0 = hbs[tc * 4 + 0], h1v = hbs[tc * 4 + 1];
        float h2 = hbs[tc * 4 + 2], h3 = hbs[tc * 4 + 3];

        float p1 = m0 * m0 + m1 * m1 + m2 * m2 + m3 * m3;
        float p2 = m0 * h0 + m1 * h1v + m2 * h2 + m3 * h3;
        float mxn2 = hsum16(p1);
        float mxy  = hsum16(p2);

        float xn;
        if (MODE == 0) xn = sAs[1152 + r];
        else           xn = __ldg(&xn_io[(gr < N) ? gr : (N - 1)]);

        float mxnr = sqrtf(mxn2);
        float mxn  = fmaxf(mxnr, EPSN);
        float tv   = tanhf(mxn / xn * artanh_f(xn));
        float rs   = tv / mxn;
        float rn   = fmaxf(mxnr * fabsf(rs), EPSN);
        float f    = (rn > BALL_MAXN) ? (BALL_MAXN / rn) : 1.0f;
        float rsf  = rs * f;

        float x2  = mxn2 * rsf * rsf;
        float xy  = mxy * rsf;
        float den = fmaxf(1.0f + 2.0f * xy + x2 * y2, EPSN);
        float ca  = (1.0f + 2.0f * xy + y2) / den;
        float cb  = (1.0f - x2) / den;

        float hn2 = ca * ca * x2 + 2.0f * ca * cb * xy + cb * cb * y2;
        float hnr = sqrtf(hn2);
        float hn  = fmaxf(hnr, EPSN);
        float cf2 = (hn > BALL_MAXN) ? (BALL_MAXN / hn) : 1.0f;
        float hna = fmaxf(hnr * cf2, EPSN);
        float lc  = artanh_f(hna) / hna;

        float Ar = lc * cf2 * ca * rsf;
        float Br = lc * cf2 * cb;

        if (gr < N) {
            float4 o = make_float4(Ar * m0 + Br * h0,  Ar * m1 + Br * h1v,
                                   Ar * m2 + Br * h2,  Ar * m3 + Br * h3);
            *(float4*)(C + (size_t)gr * DIM + tc * 4) = o;
        }
    }
}

// ---------------------------------------------------------------------------
// Gather + kC: agg = sum_e w*xt[src] over CSR list of this dst node, then
// h = proj(expmap0(agg)); xt = relu(logmap0(h)); out = proj(expmap0(xt)).
// Warp per node, 2 dims per lane.
// ---------------------------------------------------------------------------
__global__ void gather_kc_kernel(const float* __restrict__ xt,
                                 const int2* __restrict__ ed,
                                 const int* __restrict__ off,
                                 const int* __restrict__ deg,
                                 float* __restrict__ out,
                                 float* __restrict__ xn_out, int N) {
    int row  = blockIdx.x * 8 + (threadIdx.x >> 5);
    int lane = threadIdx.x & 31;
    if (row >= N) return;

    int beg = off[row];
    int dc  = deg[row];

    float ax = 0.0f, ay = 0.0f;
    for (int i0 = 0; i0 < dc; i0 += 32) {
        int i = i0 + lane;
        int2 e = (i < dc) ? __ldg(&ed[beg + i]) : make_int2(0, 0);
        int cnt = min(32, dc - i0);
        for (int j = 0; j < cnt; j++) {
            int   s  = __shfl_sync(0xffffffffu, e.x, j);
            float wt = __int_as_float(__shfl_sync(0xffffffffu, e.y, j));
            float2 v = *(const float2*)(xt + (size_t)s * DIM + lane * 2);
            ax = fmaf(wt, v.x, ax);
            ay = fmaf(wt, v.y, ay);
        }
    }

    float na2 = wsum(ax * ax + ay * ay);
    float nar = sqrtf(na2);
    float na  = fmaxf(nar, EPSN);
    float t   = tanhf(na);
    float f1  = t / na;
    float en  = fmaxf(t * (nar / na), EPSN);
    float c1  = (en > BALL_MAXN) ? (BALL_MAXN / en) : 1.0f;
    float hn  = fmaxf(en * c1, EPSN);
    float lco = artanh_f(hn) / hn * (f1 * c1);

    float lx = fmaxf(ax * lco, 0.0f);
    float ly = fmaxf(ay * lco, 0.0f);

    float nx2 = wsum(lx * lx + ly * ly);
    float nxr = sqrtf(nx2);
    float nx  = fmaxf(nxr, EPSN);
    float t2  = tanhf(nx);
    float f2  = t2 / nx;
    float en2 = fmaxf(t2 * (nxr / nx), EPSN);
    float c2  = (en2 > BALL_MAXN) ? (BALL_MAXN / en2) : 1.0f;

    float2 o = make_float2(lx * (f2 * c2), ly * (f2 * c2));
    *(float2*)(out + (size_t)row * DIM + lane * 2) = o;

    if (xn_out != nullptr && lane == 0)
        xn_out[row] = fmaxf(en2 * c2, EPSN);
}

// ---------------------------------------------------------------------------
// Launch
// ---------------------------------------------------------------------------
extern "C" void kernel_launch(void* const* d_in, const int* in_sizes, int n_in,
                              void* d_out, int out_size) {
    const float* x   = (const float*)d_in[0];
    const int*   src = (const int*)  d_in[1];
    const int*   dst = (const int*)  d_in[2];
    const float* ew  = (const float*)d_in[3];
    const float* W1  = (const float*)d_in[4];
    const float* b1  = (const float*)d_in[5];
    const float* W2  = (const float*)d_in[6];
    const float* b2  = (const float*)d_in[7];
    float* out = (float*)d_out;

    int N = in_sizes[0] / 256;
    int E = in_sizes[1];

    float *xt, *h1, *xn, *hb1, *hb2;
    int *deg, *off, *cur, *bsum, *bsumex;
    int2* edata;
    cudaGetSymbolAddress((void**)&xt,     d_xt);
    cudaGetSymbolAddress((void**)&h1,     d_h1);
    cudaGetSymbolAddress((void**)&xn,     d_xn);
    cudaGetSymbolAddress((void**)&hb1,    d_hb1);
    cudaGetSymbolAddress((void**)&hb2,    d_hb2);
    cudaGetSymbolAddress((void**)&deg,    d_deg);
    cudaGetSymbolAddress((void**)&off,    d_off);
    cudaGetSymbolAddress((void**)&cur,    d_cur);
    cudaGetSymbolAddress((void**)&bsum,   d_bsum);
    cudaGetSymbolAddress((void**)&bsumex, d_bsumex);
    cudaGetSymbolAddress((void**)&edata,  d_edata);

    int rowBlocks  = (N + 7) / 8;
    int gemmBlocks = (N + BM - 1) / BM;
    int nBlocks256 = (N + 255) / 256;
    int e4Blocks   = ((E >> 2) + 1 + 255) / 256;
    int scanBlocks = (N + 1023) / 1024;

    init_hb_kernel<<<1, 64>>>(b1, hb1);
    init_hb_kernel<<<1, 64>>>(b2, hb2);

    // ---- CSR build (shared by both layers) ----
    zero_deg_kernel<<<nBlocks256, 256>>>(deg, N);
    hist_kernel<<<e4Blocks, 256>>>(dst, deg, E);
    scan1_kernel<<<scanBlocks, 256>>>(deg, off, bsum, N);
    scan2_kernel<<<1, 256>>>(bsum, bsumex, scanBlocks);
    scan3_kernel<<<nBlocks256, 256>>>(off, cur, bsumex, N);
    fill_kernel<<<e4Blocks, 256>>>(src, dst, ew, cur, edata, E);

    // ---- layer 1 ----
    gemm_fused_kernel<0><<<gemmBlocks, 256>>>(x, W1, xt, xn, hb1, N, 256);
    gather_kc_kernel<<<rowBlocks, 256>>>(xt, edata, off, deg, h1, xn, N);

    // ---- layer 2 ----
    gemm_fused_kernel<1><<<gemmBlocks, 256>>>(h1, W2, xt, xn, hb2, N, 64);
    gather_kc_kernel<<<rowBlocks, 256>>>(xt, edata, off, deg, out, nullptr, N);
}

// round 8
// speedup vs baseline: 1.1764x; 1.1318x over previous
#include <cuda_runtime.h>
#include <cstdint>

// ============================================================================
// HGCN (2-layer hyperbolic GCN), c = 1.
//
// R8 pipeline (= R3 structure + CSR build overlapped on a forked stream):
//   main stream:  gemm<0> -> init_hb x2 -> kA1 -> [join] gather1 ->
//                 gemm<1> -> kA2 -> gather2
//   side stream:  zero_deg -> hist -> scan1..3 -> fill   (hidden under GEMM1)
// ============================================================================

#define BALL_MAXN 0.996f     // (1 - 4e-3)/sqrt(c)
#define EPSN      1e-15f
#define NODES_MAX 80000
#define E_MAX     1300000
#define DIM       64

__device__ float d_g  [NODES_MAX * DIM];
__device__ float d_xt [NODES_MAX * DIM];
__device__ float d_h1 [NODES_MAX * DIM];
__device__ float d_xn [NODES_MAX];
__device__ float d_hb1[65];
__device__ float d_hb2[65];
__device__ int   d_deg[NODES_MAX];
__device__ int   d_off[NODES_MAX];
__device__ int   d_cur[NODES_MAX];
__device__ int   d_bsum[256];
__device__ int   d_bsumex[256];
__device__ int2  d_edata[E_MAX];

__device__ __forceinline__ float wsum(float v) {
#pragma unroll
    for (int o = 16; o; o >>= 1) v += __shfl_xor_sync(0xffffffffu, v, o);
    return v;
}

__device__ __forceinline__ float artanh_f(float x) {
    x = fminf(fmaxf(x, -1.0f + 1e-7f), 1.0f - 1e-7f);
    return 0.5f * logf((1.0f + x) / (1.0f - x));
}

// ---------------------------------------------------------------------------
// hb = proj(expmap0(b)); hb[64] = ||hb||^2.  One block, 64 threads.
// ---------------------------------------------------------------------------
__global__ void init_hb_kernel(const float* __restrict__ b, float* __restrict__ hb) {
    __shared__ float sm[2];
    int t = threadIdx.x;
    float v = b[t];
    float ss = wsum(v * v);
    if ((t & 31) == 0) sm[t >> 5] = ss;
    __syncthreads();
    float tot = sm[0] + sm[1];
    __syncthreads();
    float nr = sqrtf(tot);
    float n  = fmaxf(nr, EPSN);
    float tn = tanhf(n);
    float e  = v * (tn / n);
    float en = fmaxf(tn * (nr / n), EPSN);
    float cf = (en > BALL_MAXN) ? (BALL_MAXN / en) : 1.0f;
    e *= cf;
    hb[t] = e;
    float ss2 = wsum(e * e);
    if ((t & 31) == 0) sm[t >> 5] = ss2;
    __syncthreads();
    if (t == 0) hb[64] = sm[0] + sm[1];
}

// ---------------------------------------------------------------------------
// CSR build
// ---------------------------------------------------------------------------
__global__ void zero_deg_kernel(int* __restrict__ deg, int N) {
    int i = blockIdx.x * blockDim.x + threadIdx.x;
    if (i < N) deg[i] = 0;
}

__global__ void hist_kernel(const int* __restrict__ dst, int* __restrict__ deg, int E) {
    int e = blockIdx.x * blockDim.x + threadIdx.x;
    if (e < E) atomicAdd(&deg[dst[e]], 1);
}

__global__ void scan1_kernel(const int* __restrict__ deg, int* __restrict__ off,
                             int* __restrict__ bsum, int N) {
    __shared__ int sh[256];
    int tid  = threadIdx.x;
    int base = blockIdx.x * 1024;
    int idx0 = base + tid * 4;
    int v[4];
#pragma unroll
    for (int j = 0; j < 4; j++) {
        int id = idx0 + j;
        v[j] = (id < N) ? deg[id] : 0;
    }
    int t = v[0] + v[1] + v[2] + v[3];
    sh[tid] = t;
    __syncthreads();
#pragma unroll
    for (int o = 1; o < 256; o <<= 1) {
        int u = (tid >= o) ? sh[tid - o] : 0;
        __syncthreads();
        sh[tid] += u;
        __syncthreads();
    }
    int excl = sh[tid] - t;
    int run = excl;
#pragma unroll
    for (int j = 0; j < 4; j++) {
        int id = idx0 + j;
        if (id < N) off[id] = run;
        run += v[j];
    }
    if (tid == 255) bsum[blockIdx.x] = sh[255];
}

__global__ void scan2_kernel(const int* __restrict__ bsum, int* __restrict__ bsumex, int B) {
    __shared__ int sh[256];
    int tid = threadIdx.x;
    int t = (tid < B) ? bsum[tid] : 0;
    sh[tid] = t;
    __syncthreads();
#pragma unroll
    for (int o = 1; o < 256; o <<= 1) {
        int u = (tid >= o) ? sh[tid - o] : 0;
        __syncthreads();
        sh[tid] += u;
        __syncthreads();
    }
    if (tid < B) bsumex[tid] = sh[tid] - t;
}

__global__ void scan3_kernel(int* __restrict__ off, int* __restrict__ cur,
                             const int* __restrict__ bsumex, int N) {
    int i = blockIdx.x * blockDim.x + threadIdx.x;
    if (i < N) {
        int v = off[i] + bsumex[i >> 10];
        off[i] = v;
        cur[i] = v;
    }
}

__global__ void fill_kernel(const int* __restrict__ src, const int* __restrict__ dst,
                            const float* __restrict__ w, int* __restrict__ cur,
                            int2* __restrict__ ed, int E) {
    int e = blockIdx.x * blockDim.x + threadIdx.x;
    if (e >= E) return;
    int d = dst[e];
    int pos = atomicAdd(&cur[d], 1);
    ed[pos] = make_int2(src[e], __float_as_int(w[e]));
}

// ---------------------------------------------------------------------------
// GEMM: C[N,64] = A[N,K] @ W[64,K]^T.  MODE 0: fused encode scale + xn out.
// BM=128, BN=64, BK=32, 256 threads, 8x4 register tile.
// ---------------------------------------------------------------------------
#define BM 128
#define BN 64
#define BK 32

template <int MODE>
__global__ __launch_bounds__(256, 2)
void gemm_kernel(const float* __restrict__ A, const float* __restrict__ W,
                 float* __restrict__ C, float* __restrict__ xn_out, int N, int K) {
    __shared__ float As[BK][BM];  // k-major
    __shared__ float Ws[BK][BN];
    __shared__ float sred[4][256];
    __shared__ float snorm[BM];

    int tid = threadIdx.x;
    int block_row = blockIdx.x * BM;
    int tr = tid >> 4;   // rows tr*8 .. +7
    int tc = tid & 15;   // cols tc*4 .. +3

    float acc[8][4];
#pragma unroll
    for (int i = 0; i < 8; i++)
#pragma unroll
        for (int j = 0; j < 4; j++) acc[i][j] = 0.0f;
    float ssl[4] = {0.f, 0.f, 0.f, 0.f};

    for (int k0 = 0; k0 < K; k0 += BK) {
#pragma unroll
        for (int i = 0; i < 4; i++) {
            int idx = tid + i * 256;
            int r   = idx >> 3;
            int kq  = (idx & 7) << 2;
            int gr  = block_row + r;
            if (gr >= N) gr = N - 1;
            float4 v = *(const float4*)(A + (size_t)gr * K + k0 + kq);
            As[kq + 0][r] = v.x; As[kq + 1][r] = v.y;
            As[kq + 2][r] = v.z; As[kq + 3][r] = v.w;
            if (MODE == 0)
                ssl[i] += v.x * v.x + v.y * v.y + v.z * v.z + v.w * v.w;
        }
#pragma unroll
        for (int i = 0; i < 2; i++) {
            int idx = tid + i * 256;
            int c   = idx >> 3;
            int kq  = (idx & 7) << 2;
            float4 v = *(const float4*)(W + (size_t)c * K + k0 + kq);
            Ws[kq + 0][c] = v.x; Ws[kq + 1][c] = v.y;
            Ws[kq + 2][c] = v.z; Ws[kq + 3][c] = v.w;
        }
        __syncthreads();

#pragma unroll
        for (int kk = 0; kk < BK; kk++) {
            float4 a0 = *(const float4*)&As[kk][tr * 8];
            float4 a1 = *(const float4*)&As[kk][tr * 8 + 4];
            float4 b  = *(const float4*)&Ws[kk][tc * 4];
            float av[8] = {a0.x, a0.y, a0.z, a0.w, a1.x, a1.y, a1.z, a1.w};
            float bv[4] = {b.x, b.y, b.z, b.w};
#pragma unroll
            for (int i = 0; i < 8; i++)
#pragma unroll
                for (int j = 0; j < 4; j++)
                    acc[i][j] = fmaf(av[i], bv[j], acc[i][j]);
        }
        __syncthreads();
    }

    if (MODE == 0) {
        sred[0][tid] = ssl[0]; sred[1][tid] = ssl[1];
        sred[2][tid] = ssl[2]; sred[3][tid] = ssl[3];
        __syncthreads();
        if (tid < 128) {
            int r   = tid;
            int grp = r >> 5;
            int t0  = (r & 31) << 3;
            float s2 = 0.0f;
#pragma unroll
            for (int j = 0; j < 8; j++) s2 += sred[grp][t0 + j];
            snorm[r] = s2;
        }
        __syncthreads();
    }

#pragma unroll
    for (int i = 0; i < 8; i++) {
        int r  = tr * 8 + i;
        int gr = block_row + r;
        if (gr >= N) continue;
        float sc = 1.0f;
        if (MODE == 0) {
            float nxr = sqrtf(snorm[r]);
            float nx  = fmaxf(nxr, EPSN);
            float t   = tanhf(nx);
            float en  = fmaxf(t * (nxr / nx), EPSN);    // ||expmap0(x)||
            float cf  = (en > BALL_MAXN) ? (BALL_MAXN / en) : 1.0f;
            sc = (t / nx) * cf;                          // h0 = sc * x
            if (tc == 0) xn_out[gr] = fmaxf(en * cf, EPSN);
        }
        float4 o = make_float4(acc[i][0] * sc, acc[i][1] * sc,
                               acc[i][2] * sc, acc[i][3] * sc);
        *(float4*)(C + (size_t)gr * DIM + tc * 4) = o;
    }
}

// ---------------------------------------------------------------------------
// kA: mv = proj(mobius_matvec tail); h = proj(mobius_add(mv, hb)); xt = logmap0.
// Warp per row, 2 dims per lane. xn (= _norm of layer input) given per row.
// ---------------------------------------------------------------------------
__global__ void kA_kernel(const float* __restrict__ g,
                          const float* __restrict__ xnarr,
                          const float* __restrict__ hb,
                          float* __restrict__ xt_out, int N) {
    int row  = blockIdx.x * 8 + (threadIdx.x >> 5);
    int lane = threadIdx.x & 31;
    if (row >= N) return;

    float2 mx = *(const float2*)(g + (size_t)row * DIM + lane * 2);
    float xn = xnarr[row];

    float mxn2 = wsum(mx.x * mx.x + mx.y * mx.y);
    float mxnr = sqrtf(mxn2);
    float mxn  = fmaxf(mxnr, EPSN);
    float tv   = tanhf(mxn / xn * artanh_f(xn));
    float rs   = tv / mxn;
    float rx = mx.x * rs, ry = mx.y * rs;

    float rn = fmaxf(mxnr * fabsf(rs), EPSN);
    if (rn > BALL_MAXN) { float f = BALL_MAXN / rn; rx *= f; ry *= f; }

    float hbx = hb[lane * 2], hby = hb[lane * 2 + 1];
    float y2  = hb[64];
    float x2  = wsum(rx * rx + ry * ry);
    float xy  = wsum(rx * hbx + ry * hby);
    float den = fmaxf(1.0f + 2.0f * xy + x2 * y2, EPSN);
    float ca  = (1.0f + 2.0f * xy + y2) / den;
    float cb  = (1.0f - x2) / den;
    float hx = ca * rx + cb * hbx;
    float hy = ca * ry + cb * hby;

    float hn2 = wsum(hx * hx + hy * hy);
    float hnr = sqrtf(hn2);
    float hn  = fmaxf(hnr, EPSN);
    float cf2 = (hn > BALL_MAXN) ? (BALL_MAXN / hn) : 1.0f;
    hx *= cf2; hy *= cf2;

    float hna = fmaxf(hnr * cf2, EPSN);
    float lc  = artanh_f(hna) / hna;
    float2 o = make_float2(hx * lc, hy * lc);
    *(float2*)(xt_out + (size_t)row * DIM + lane * 2) = o;
}

// ---------------------------------------------------------------------------
// Gather + kC: agg = sum_e w*xt[src] over CSR list of this dst node, then
// h = proj(expmap0(agg)); xt = relu(logmap0(h)); out = proj(expmap0(xt)).
// Warp per node, 2 dims per lane.
// ---------------------------------------------------------------------------
__global__ void gather_kc_kernel(const float* __restrict__ xt,
                                 const int2* __restrict__ ed,
                                 const int* __restrict__ off,
                                 const int* __restrict__ deg,
                                 float* __restrict__ out,
                                 float* __restrict__ xn_out, int N) {
    int row  = blockIdx.x * 8 + (threadIdx.x >> 5);
    int lane = threadIdx.x & 31;
    if (row >= N) return;

    int beg = off[row];
    int dc  = deg[row];

    float ax = 0.0f, ay = 0.0f;
    for (int i0 = 0; i0 < dc; i0 += 32) {
        int i = i0 + lane;
        int2 e = (i < dc) ? __ldg(&ed[beg + i]) : make_int2(0, 0);
        int cnt = min(32, dc - i0);
        for (int j = 0; j < cnt; j++) {
            int   s  = __shfl_sync(0xffffffffu, e.x, j);
            float wt = __int_as_float(__shfl_sync(0xffffffffu, e.y, j));
            float2 v = *(const float2*)(xt + (size_t)s * DIM + lane * 2);
            ax = fmaf(wt, v.x, ax);
            ay = fmaf(wt, v.y, ay);
        }
    }

    float na2 = wsum(ax * ax + ay * ay);
    float nar = sqrtf(na2);
    float na  = fmaxf(nar, EPSN);
    float t   = tanhf(na);
    float f1  = t / na;
    float en  = fmaxf(t * (nar / na), EPSN);
    float c1  = (en > BALL_MAXN) ? (BALL_MAXN / en) : 1.0f;
    float hn  = fmaxf(en * c1, EPSN);
    float lco = artanh_f(hn) / hn * (f1 * c1);

    float lx = fmaxf(ax * lco, 0.0f);
    float ly = fmaxf(ay * lco, 0.0f);

    float nx2 = wsum(lx * lx + ly * ly);
    float nxr = sqrtf(nx2);
    float nx  = fmaxf(nxr, EPSN);
    float t2  = tanhf(nx);
    float f2  = t2 / nx;
    float en2 = fmaxf(t2 * (nxr / nx), EPSN);
    float c2  = (en2 > BALL_MAXN) ? (BALL_MAXN / en2) : 1.0f;

    float2 o = make_float2(lx * (f2 * c2), ly * (f2 * c2));
    *(float2*)(out + (size_t)row * DIM + lane * 2) = o;

    if (xn_out != nullptr && lane == 0)
        xn_out[row] = fmaxf(en2 * c2, EPSN);
}

// ---------------------------------------------------------------------------
// Launch: CSR build forked onto a side stream, hidden under GEMM1 + kA1.
// ---------------------------------------------------------------------------
extern "C" void kernel_launch(void* const* d_in, const int* in_sizes, int n_in,
                              void* d_out, int out_size) {
    const float* x   = (const float*)d_in[0];
    const int*   src = (const int*)  d_in[1];
    const int*   dst = (const int*)  d_in[2];
    const float* ew  = (const float*)d_in[3];
    const float* W1  = (const float*)d_in[4];
    const float* b1  = (const float*)d_in[5];
    const float* W2  = (const float*)d_in[6];
    const float* b2  = (const float*)d_in[7];
    float* out = (float*)d_out;

    int N = in_sizes[0] / 256;
    int E = in_sizes[1];

    float *g, *xt, *h1, *xn, *hb1, *hb2;
    int *deg, *off, *cur, *bsum, *bsumex;
    int2* edata;
    cudaGetSymbolAddress((void**)&g,      d_g);
    cudaGetSymbolAddress((void**)&xt,     d_xt);
    cudaGetSymbolAddress((void**)&h1,     d_h1);
    cudaGetSymbolAddress((void**)&xn,     d_xn);
    cudaGetSymbolAddress((void**)&hb1,    d_hb1);
    cudaGetSymbolAddress((void**)&hb2,    d_hb2);
    cudaGetSymbolAddress((void**)&deg,    d_deg);
    cudaGetSymbolAddress((void**)&off,    d_off);
    cudaGetSymbolAddress((void**)&cur,    d_cur);
    cudaGetSymbolAddress((void**)&bsum,   d_bsum);
    cudaGetSymbolAddress((void**)&bsumex, d_bsumex);
    cudaGetSymbolAddress((void**)&edata,  d_edata);

    int rowBlocks  = (N + 7) / 8;
    int gemmBlocks = (N + BM - 1) / BM;
    int nBlocks256 = (N + 255) / 256;
    int eBlocks256 = (E + 255) / 256;
    int scanBlocks = (N + 1023) / 1024;

    cudaStream_t s1;
    cudaStreamCreateWithFlags(&s1, cudaStreamNonBlocking);
    cudaEvent_t e0, e1;
    cudaEventCreateWithFlags(&e0, cudaEventDisableTiming);
    cudaEventCreateWithFlags(&e1, cudaEventDisableTiming);

    // fork: side stream handles the CSR build (independent of GEMM1/kA1)
    cudaEventRecord(e0, 0);
    cudaStreamWaitEvent(s1, e0, 0);

    zero_deg_kernel<<<nBlocks256, 256, 0, s1>>>(deg, N);
    hist_kernel<<<eBlocks256, 256, 0, s1>>>(dst, deg, E);
    scan1_kernel<<<scanBlocks, 256, 0, s1>>>(deg, off, bsum, N);
    scan2_kernel<<<1, 256, 0, s1>>>(bsum, bsumex, scanBlocks);
    scan3_kernel<<<nBlocks256, 256, 0, s1>>>(off, cur, bsumex, N);
    fill_kernel<<<eBlocks256, 256, 0, s1>>>(src, dst, ew, cur, edata, E);
    cudaEventRecord(e1, s1);

    // main stream: layer-1 dense work (runs concurrently with CSR build)
    gemm_kernel<0><<<gemmBlocks, 256>>>(x, W1, g, xn, N, 256);
    init_hb_kernel<<<1, 64>>>(b1, hb1);
    init_hb_kernel<<<1, 64>>>(b2, hb2);
    kA_kernel<<<rowBlocks, 256>>>(g, xn, hb1, xt, N);

    // join: gather needs the CSR
    cudaStreamWaitEvent(0, e1, 0);
    gather_kc_kernel<<<rowBlocks, 256>>>(xt, edata, off, deg, h1, xn, N);

    // ---- layer 2 ----
    gemm_kernel<1><<<gemmBlocks, 256>>>(h1, W2, g, nullptr, N, 64);
    kA_kernel<<<rowBlocks, 256>>>(g, xn, hb2, xt, N);
    gather_kc_kernel<<<rowBlocks, 256>>>(xt, edata, off, deg, out, nullptr, N);

    cudaEventDestroy(e0);
    cudaEventDestroy(e1);
    cudaStreamDestroy(s1);
}

// round 9
// speedup vs baseline: 1.2415x; 1.0553x over previous
#include <cuda_runtime.h>
#include <cuda_bf16.h>
#include <cstdint>

// ============================================================================
// HGCN (2-layer hyperbolic GCN), c = 1.
//
// R9 pipeline (= R8 + tensor-core GEMMs via bf16-split mma.sync):
//   main stream:  wsplit(W1) -> wsplit(W2) -> mmaGEMM<0>(x,W1) ->
//                 [join hb] kA1 -> [join csr] gather1 ->
//                 mmaGEMM<1>(h1,W2) -> kA2 -> gather2
//   side stream:  init_hb x2 -> zero_deg -> hist -> scan1..3 -> fill
//
// GEMM math: fp32 operands split a = hi + lo (bf16 each);
//   a*b ~= ah*bh + ah*bl + al*bh  (residual ~2^-16, well under 1e-3 budget)
// ============================================================================

#define BALL_MAXN 0.996f     // (1 - 4e-3)/sqrt(c)
#define EPSN      1e-15f
#define NODES_MAX 80000
#define E_MAX     1300000
#define DIM       64

__device__ float d_g  [NODES_MAX * DIM];
__device__ float d_xt [NODES_MAX * DIM];
__device__ float d_h1 [NODES_MAX * DIM];
__device__ float d_xn [NODES_MAX];
__device__ float d_hb1[65];
__device__ float d_hb2[65];
__device__ int   d_deg[NODES_MAX];
__device__ int   d_off[NODES_MAX];
__device__ int   d_cur[NODES_MAX];
__device__ int   d_bsum[256];
__device__ int   d_bsumex[256];
__device__ int2  d_edata[E_MAX];
__device__ unsigned d_whi1[64 * 256 / 2];
__device__ unsigned d_wlo1[64 * 256 / 2];
__device__ unsigned d_whi2[64 * 64 / 2];
__device__ unsigned d_wlo2[64 * 64 / 2];

__device__ __forceinline__ float wsum(float v) {
#pragma unroll
    for (int o = 16; o; o >>= 1) v += __shfl_xor_sync(0xffffffffu, v, o);
    return v;
}

__device__ __forceinline__ float artanh_f(float x) {
    x = fminf(fmaxf(x, -1.0f + 1e-7f), 1.0f - 1e-7f);
    return 0.5f * logf((1.0f + x) / (1.0f - x));
}

// split a pair of fp32 into packed bf16x2 (hi) and bf16x2 (lo residual).
// lo half of the b32 = element with the smaller index (f0).
__device__ __forceinline__ void split2(float f0, float f1,
                                       unsigned& hi, unsigned& lo) {
    asm("cvt.rn.bf16x2.f32 %0, %1, %2;" : "=r"(hi) : "f"(f1), "f"(f0));
    float h0 = __uint_as_float(hi << 16);
    float h1 = __uint_as_float(hi & 0xffff0000u);
    float l0 = f0 - h0;
    float l1 = f1 - h1;
    asm("cvt.rn.bf16x2.f32 %0, %1, %2;" : "=r"(lo) : "f"(l1), "f"(l0));
}

#define MMA_BF16(d, a0, a1, a2, a3, b0, b1) \
    asm volatile("mma.sync.aligned.m16n8k16.row.col.f32.bf16.bf16.f32 " \
        "{%0,%1,%2,%3}, {%4,%5,%6,%7}, {%8,%9}, {%0,%1,%2,%3};" \
        : "+f"((d)[0]), "+f"((d)[1]), "+f"((d)[2]), "+f"((d)[3]) \
        : "r"(a0), "r"(a1), "r"(a2), "r"(a3), "r"(b0), "r"(b1))

// ---------------------------------------------------------------------------
// W split: fp32 [rows,K] -> packed bf16x2 hi/lo arrays (pairs along K).
// ---------------------------------------------------------------------------
__global__ void wsplit_kernel(const float* __restrict__ W,
                              unsigned* __restrict__ whi,
                              unsigned* __restrict__ wlo, int npairs) {
    int i = blockIdx.x * blockDim.x + threadIdx.x;
    if (i < npairs) {
        float2 f = ((const float2*)W)[i];
        unsigned hi, lo;
        split2(f.x, f.y, hi, lo);
        whi[i] = hi;
        wlo[i] = lo;
    }
}

// ---------------------------------------------------------------------------
// hb = proj(expmap0(b)); hb[64] = ||hb||^2.  One block, 64 threads.
// ---------------------------------------------------------------------------
__global__ void init_hb_kernel(const float* __restrict__ b, float* __restrict__ hb) {
    __shared__ float sm[2];
    int t = threadIdx.x;
    float v = b[t];
    float ss = wsum(v * v);
    if ((t & 31) == 0) sm[t >> 5] = ss;
    __syncthreads();
    float tot = sm[0] + sm[1];
    __syncthreads();
    float nr = sqrtf(tot);
    float n  = fmaxf(nr, EPSN);
    float tn = tanhf(n);
    float e  = v * (tn / n);
    float en = fmaxf(tn * (nr / n), EPSN);
    float cf = (en > BALL_MAXN) ? (BALL_MAXN / en) : 1.0f;
    e *= cf;
    hb[t] = e;
    float ss2 = wsum(e * e);
    if ((t & 31) == 0) sm[t >> 5] = ss2;
    __syncthreads();
    if (t == 0) hb[64] = sm[0] + sm[1];
}

// ---------------------------------------------------------------------------
// CSR build
// ---------------------------------------------------------------------------
__global__ void zero_deg_kernel(int* __restrict__ deg, int N) {
    int i = blockIdx.x * blockDim.x + threadIdx.x;
    if (i < N) deg[i] = 0;
}

__global__ void hist_kernel(const int* __restrict__ dst, int* __restrict__ deg, int E) {
    int e = blockIdx.x * blockDim.x + threadIdx.x;
    if (e < E) atomicAdd(&deg[dst[e]], 1);
}

__global__ void scan1_kernel(const int* __restrict__ deg, int* __restrict__ off,
                             int* __restrict__ bsum, int N) {
    __shared__ int sh[256];
    int tid  = threadIdx.x;
    int base = blockIdx.x * 1024;
    int idx0 = base + tid * 4;
    int v[4];
#pragma unroll
    for (int j = 0; j < 4; j++) {
        int id = idx0 + j;
        v[j] = (id < N) ? deg[id] : 0;
    }
    int t = v[0] + v[1] + v[2] + v[3];
    sh[tid] = t;
    __syncthreads();
#pragma unroll
    for (int o = 1; o < 256; o <<= 1) {
        int u = (tid >= o) ? sh[tid - o] : 0;
        __syncthreads();
        sh[tid] += u;
        __syncthreads();
    }
    int excl = sh[tid] - t;
    int run = excl;
#pragma unroll
    for (int j = 0; j < 4; j++) {
        int id = idx0 + j;
        if (id < N) off[id] = run;
        run += v[j];
    }
    if (tid == 255) bsum[blockIdx.x] = sh[255];
}

__global__ void scan2_kernel(const int* __restrict__ bsum, int* __restrict__ bsumex, int B) {
    __shared__ int sh[256];
    int tid = threadIdx.x;
    int t = (tid < B) ? bsum[tid] : 0;
    sh[tid] = t;
    __syncthreads();
#pragma unroll
    for (int o = 1; o < 256; o <<= 1) {
        int u = (tid >= o) ? sh[tid - o] : 0;
        __syncthreads();
        sh[tid] += u;
        __syncthreads();
    }
    if (tid < B) bsumex[tid] = sh[tid] - t;
}

__global__ void scan3_kernel(int* __restrict__ off, int* __restrict__ cur,
                             const int* __restrict__ bsumex, int N) {
    int i = blockIdx.x * blockDim.x + threadIdx.x;
    if (i < N) {
        int v = off[i] + bsumex[i >> 10];
        off[i] = v;
        cur[i] = v;
    }
}

__global__ void fill_kernel(const int* __restrict__ src, const int* __restrict__ dst,
                            const float* __restrict__ w, int* __restrict__ cur,
                            int2* __restrict__ ed, int E) {
    int e = blockIdx.x * blockDim.x + threadIdx.x;
    if (e >= E) return;
    int d = dst[e];
    int pos = atomicAdd(&cur[d], 1);
    ed[pos] = make_int2(src[e], __float_as_int(w[e]));
}

// ---------------------------------------------------------------------------
// Tensor-core GEMM: C[N,64] = A[N,K] @ W[64,K]^T   (fp32 via bf16 split).
// Tile M=128, N=64, BK=32. 8 warps: warp grid 4(m) x 2(n); each warp 32x32.
// MODE 0: fused encode scale (h0 = s(||x||)*x folded into C) + xn out.
// ---------------------------------------------------------------------------
#define BM 128
#define KPAD 17   // 16 bf16x2 pairs per 32-wide k-slab + 1 pad

template <int MODE, int K>
__global__ __launch_bounds__(256, 2)
void gemm_mma_kernel(const float* __restrict__ A,
                     const unsigned* __restrict__ whi,
                     const unsigned* __restrict__ wlo,
                     float* __restrict__ C, float* __restrict__ xn_io, int N) {
    __shared__ unsigned Ahi[BM * KPAD];
    __shared__ unsigned Alo[BM * KPAD];
    __shared__ float sred[4 * 256];
    __shared__ float ssc[BM];

    int tid  = threadIdx.x;
    int lane = tid & 31;
    int wid  = tid >> 5;
    int warp_m = wid >> 1;        // 0..3  -> m offset warp_m*32
    int warp_n = wid & 1;         // 0..1  -> n offset warp_n*32
    int block_row = blockIdx.x * BM;

    int qrow = lane >> 2;         // 0..7
    int qcol = lane & 3;          // 0..3

    float acc[2][4][4];           // [mt][nt][reg]
#pragma unroll
    for (int mt = 0; mt < 2; mt++)
#pragma unroll
        for (int nt = 0; nt < 4; nt++)
#pragma unroll
            for (int r = 0; r < 4; r++) acc[mt][nt][r] = 0.0f;

    float ssl[4] = {0.f, 0.f, 0.f, 0.f};

    for (int k0 = 0; k0 < K; k0 += 32) {
        // ---- stage A tile (128x32 fp32), split to bf16x2 hi/lo in smem ----
#pragma unroll
        for (int i = 0; i < 4; i++) {
            int idx = tid + i * 256;          // 0..1023
            int r   = idx >> 3;               // 0..127
            int kq  = (idx & 7) << 2;         // 0,4,...,28
            int gr  = block_row + r;
            if (gr >= N) gr = N - 1;
            float4 v = *(const float4*)(A + (size_t)gr * K + k0 + kq);
            unsigned h0, l0, h1, l1;
            split2(v.x, v.y, h0, l0);
            split2(v.z, v.w, h1, l1);
            Ahi[r * KPAD + (kq >> 1)]     = h0;
            Alo[r * KPAD + (kq >> 1)]     = l0;
            Ahi[r * KPAD + (kq >> 1) + 1] = h1;
            Alo[r * KPAD + (kq >> 1) + 1] = l1;
            if (MODE == 0)
                ssl[i] += v.x * v.x + v.y * v.y + v.z * v.z + v.w * v.w;
        }
        __syncthreads();

#pragma unroll
        for (int kc = 0; kc < 2; kc++) {
            int pc = kc * 8 + qcol;           // bf16x2 pair index within slab
            // ---- A fragments (2 m-tiles) ----
            unsigned ah[2][4], al[2][4];
#pragma unroll
            for (int mt = 0; mt < 2; mt++) {
                int r0 = warp_m * 32 + mt * 16 + qrow;
                ah[mt][0] = Ahi[r0 * KPAD + pc];
                ah[mt][1] = Ahi[(r0 + 8) * KPAD + pc];
                ah[mt][2] = Ahi[r0 * KPAD + pc + 4];
                ah[mt][3] = Ahi[(r0 + 8) * KPAD + pc + 4];
                al[mt][0] = Alo[r0 * KPAD + pc];
                al[mt][1] = Alo[(r0 + 8) * KPAD + pc];
                al[mt][2] = Alo[r0 * KPAD + pc + 4];
                al[mt][3] = Alo[(r0 + 8) * KPAD + pc + 4];
            }
            // ---- B fragments (4 n-tiles) from pre-split W (L1-resident) ----
#pragma unroll
            for (int nt = 0; nt < 4; nt++) {
                int n  = warp_n * 32 + nt * 8 + qrow;
                int kp = (k0 + kc * 16) / 2 + qcol;       // pair idx within row
                int bidx = n * (K / 2) + kp;
                unsigned bh0 = __ldg(&whi[bidx]);
                unsigned bh1 = __ldg(&whi[bidx + 4]);
                unsigned bl0 = __ldg(&wlo[bidx]);
                unsigned bl1 = __ldg(&wlo[bidx + 4]);
#pragma unroll
                for (int mt = 0; mt < 2; mt++) {
                    MMA_BF16(acc[mt][nt], ah[mt][0], ah[mt][1], ah[mt][2], ah[mt][3], bh0, bh1);
                    MMA_BF16(acc[mt][nt], ah[mt][0], ah[mt][1], ah[mt][2], ah[mt][3], bl0, bl1);
                    MMA_BF16(acc[mt][nt], al[mt][0], al[mt][1], al[mt][2], al[mt][3], bh0, bh1);
                }
            }
        }
        __syncthreads();
    }

    // ---- MODE 0: per-row encode scale + xn ----
    if (MODE == 0) {
        sred[0 * 256 + tid] = ssl[0];
        sred[1 * 256 + tid] = ssl[1];
        sred[2 * 256 + tid] = ssl[2];
        sred[3 * 256 + tid] = ssl[3];
        __syncthreads();
        if (tid < 128) {
            int r   = tid;
            int grp = r >> 5;
            int t0  = (r & 31) << 3;
            float s2 = 0.0f;
#pragma unroll
            for (int j = 0; j < 8; j++) s2 += sred[grp * 256 + t0 + j];
            float nxr = sqrtf(s2);
            float nx  = fmaxf(nxr, EPSN);
            float t   = tanhf(nx);
            float en  = fmaxf(t * (nxr / nx), EPSN);     // ||expmap0(x)||
            float cf  = (en > BALL_MAXN) ? (BALL_MAXN / en) : 1.0f;
            ssc[r] = (t / nx) * cf;                       // h0 = sc * x
            int gr = block_row + r;
            if (gr < N) xn_io[gr] = fmaxf(en * cf, EPSN);
        }
        __syncthreads();
    }

    // ---- write C (scaled in MODE 0) ----
#pragma unroll
    for (int mt = 0; mt < 2; mt++) {
#pragma unroll
        for (int nt = 0; nt < 4; nt++) {
            int r0 = warp_m * 32 + mt * 16 + qrow;
            int c  = warp_n * 32 + nt * 8 + qcol * 2;
            int gr0 = block_row + r0;
            int gr1 = gr0 + 8;
            if (gr0 < N) {
                float sc = (MODE == 0) ? ssc[r0] : 1.0f;
                float2 o = make_float2(acc[mt][nt][0] * sc, acc[mt][nt][1] * sc);
                *(float2*)(C + (size_t)gr0 * DIM + c) = o;
            }
            if (gr1 < N) {
                float sc = (MODE == 0) ? ssc[r0 + 8] : 1.0f;
                float2 o = make_float2(acc[mt][nt][2] * sc, acc[mt][nt][3] * sc);
                *(float2*)(C + (size_t)gr1 * DIM + c) = o;
            }
        }
    }
}

// ---------------------------------------------------------------------------
// kA: mv = proj(mobius_matvec tail); h = proj(mobius_add(mv, hb)); xt = logmap0.
// Warp per row, 2 dims per lane. xn (= _norm of layer input) given per row.
// ---------------------------------------------------------------------------
__global__ void kA_kernel(const float* __restrict__ g,
                          const float* __restrict__ xnarr,
                          const float* __restrict__ hb,
                          float* __restrict__ xt_out, int N) {
    int row  = blockIdx.x * 8 + (threadIdx.x >> 5);
    int lane = threadIdx.x & 31;
    if (row >= N) return;

    float2 mx = *(const float2*)(g + (size_t)row * DIM + lane * 2);
    float xn = xnarr[row];

    float mxn2 = wsum(mx.x * mx.x + mx.y * mx.y);
    float mxnr = sqrtf(mxn2);
    float mxn  = fmaxf(mxnr, EPSN);
    float tv   = tanhf(mxn / xn * artanh_f(xn));
    float rs   = tv / mxn;
    float rx = mx.x * rs, ry = mx.y * rs;

    float rn = fmaxf(mxnr * fabsf(rs), EPSN);
    if (rn > BALL_MAXN) { float f = BALL_MAXN / rn; rx *= f; ry *= f; }

    float hbx = hb[lane * 2], hby = hb[lane * 2 + 1];
    float y2  = hb[64];
    float x2  = wsum(rx * rx + ry * ry);
    float xy  = wsum(rx * hbx + ry * hby);
    float den = fmaxf(1.0f + 2.0f * xy + x2 * y2, EPSN);
    float ca  = (1.0f + 2.0f * xy + y2) / den;
    float cb  = (1.0f - x2) / den;
    float hx = ca * rx + cb * hbx;
    float hy = ca * ry + cb * hby;

    float hn2 = wsum(hx * hx + hy * hy);
    float hnr = sqrtf(hn2);
    float hn  = fmaxf(hnr, EPSN);
    float cf2 = (hn > BALL_MAXN) ? (BALL_MAXN / hn) : 1.0f;
    hx *= cf2; hy *= cf2;

    float hna = fmaxf(hnr * cf2, EPSN);
    float lc  = artanh_f(hna) / hna;
    float2 o = make_float2(hx * lc, hy * lc);
    *(float2*)(xt_out + (size_t)row * DIM + lane * 2) = o;
}

// ---------------------------------------------------------------------------
// Gather + kC: agg = sum_e w*xt[src] over CSR list of this dst node, then
// h = proj(expmap0(agg)); xt = relu(logmap0(h)); out = proj(expmap0(xt)).
// Warp per node, 2 dims per lane.
// ---------------------------------------------------------------------------
__global__ void gather_kc_kernel(const float* __restrict__ xt,
                                 const int2* __restrict__ ed,
                                 const int* __restrict__ off,
                                 const int* __restrict__ deg,
                                 float* __restrict__ out,
                                 float* __restrict__ xn_out, int N) {
    int row  = blockIdx.x * 8 + (threadIdx.x >> 5);
    int lane = threadIdx.x & 31;
    if (row >= N) return;

    int beg = off[row];
    int dc  = deg[row];

    float ax = 0.0f, ay = 0.0f;
    for (int i0 = 0; i0 < dc; i0 += 32) {
        int i = i0 + lane;
        int2 e = (i < dc) ? __ldg(&ed[beg + i]) : make_int2(0, 0);
        int cnt = min(32, dc - i0);
        for (int j = 0; j < cnt; j++) {
            int   s  = __shfl_sync(0xffffffffu, e.x, j);
            float wt = __int_as_float(__shfl_sync(0xffffffffu, e.y, j));
            float2 v = *(const float2*)(xt + (size_t)s * DIM + lane * 2);
            ax = fmaf(wt, v.x, ax);
            ay = fmaf(wt, v.y, ay);
        }
    }

    float na2 = wsum(ax * ax + ay * ay);
    float nar = sqrtf(na2);
    float na  = fmaxf(nar, EPSN);
    float t   = tanhf(na);
    float f1  = t / na;
    float en  = fmaxf(t * (nar / na), EPSN);
    float c1  = (en > BALL_MAXN) ? (BALL_MAXN / en) : 1.0f;
    float hn  = fmaxf(en * c1, EPSN);
    float lco = artanh_f(hn) / hn * (f1 * c1);

    float lx = fmaxf(ax * lco, 0.0f);
    float ly = fmaxf(ay * lco, 0.0f);

    float nx2 = wsum(lx * lx + ly * ly);
    float nxr = sqrtf(nx2);
    float nx  = fmaxf(nxr, EPSN);
    float t2  = tanhf(nx);
    float f2  = t2 / nx;
    float en2 = fmaxf(t2 * (nxr / nx), EPSN);
    float c2  = (en2 > BALL_MAXN) ? (BALL_MAXN / en2) : 1.0f;

    float2 o = make_float2(lx * (f2 * c2), ly * (f2 * c2));
    *(float2*)(out + (size_t)row * DIM + lane * 2) = o;

    if (xn_out != nullptr && lane == 0)
        xn_out[row] = fmaxf(en2 * c2, EPSN);
}

// ---------------------------------------------------------------------------
// Launch: CSR build + hb init on side stream, hidden under W split + GEMM1.
// ---------------------------------------------------------------------------
extern "C" void kernel_launch(void* const* d_in, const int* in_sizes, int n_in,
                              void* d_out, int out_size) {
    const float* x   = (const float*)d_in[0];
    const int*   src = (const int*)  d_in[1];
    const int*   dst = (const int*)  d_in[2];
    const float* ew  = (const float*)d_in[3];
    const float* W1  = (const float*)d_in[4];
    const float* b1  = (const float*)d_in[5];
    const float* W2  = (const float*)d_in[6];
    const float* b2  = (const float*)d_in[7];
    float* out = (float*)d_out;

    int N = in_sizes[0] / 256;
    int E = in_sizes[1];

    float *g, *xt, *h1, *xn, *hb1, *hb2;
    int *deg, *off, *cur, *bsum, *bsumex;
    int2* edata;
    unsigned *whi1, *wlo1, *whi2, *wlo2;
    cudaGetSymbolAddress((void**)&g,      d_g);
    cudaGetSymbolAddress((void**)&xt,     d_xt);
    cudaGetSymbolAddress((void**)&h1,     d_h1);
    cudaGetSymbolAddress((void**)&xn,     d_xn);
    cudaGetSymbolAddress((void**)&hb1,    d_hb1);
    cudaGetSymbolAddress((void**)&hb2,    d_hb2);
    cudaGetSymbolAddress((void**)&deg,    d_deg);
    cudaGetSymbolAddress((void**)&off,    d_off);
    cudaGetSymbolAddress((void**)&cur,    d_cur);
    cudaGetSymbolAddress((void**)&bsum,   d_bsum);
    cudaGetSymbolAddress((void**)&bsumex, d_bsumex);
    cudaGetSymbolAddress((void**)&edata,  d_edata);
    cudaGetSymbolAddress((void**)&whi1,   d_whi1);
    cudaGetSymbolAddress((void**)&wlo1,   d_wlo1);
    cudaGetSymbolAddress((void**)&whi2,   d_whi2);
    cudaGetSymbolAddress((void**)&wlo2,   d_wlo2);

    int rowBlocks  = (N + 7) / 8;
    int gemmBlocks = (N + BM - 1) / BM;
    int nBlocks256 = (N + 255) / 256;
    int eBlocks256 = (E + 255) / 256;
    int scanBlocks = (N + 1023) / 1024;

    cudaStream_t s1;
    cudaStreamCreateWithFlags(&s1, cudaStreamNonBlocking);
    cudaEvent_t e0, e_hb, e_csr;
    cudaEventCreateWithFlags(&e0,    cudaEventDisableTiming);
    cudaEventCreateWithFlags(&e_hb,  cudaEventDisableTiming);
    cudaEventCreateWithFlags(&e_csr, cudaEventDisableTiming);

    // fork
    cudaEventRecord(e0, 0);
    cudaStreamWaitEvent(s1, e0, 0);

    // side stream: hb constants, then CSR build
    init_hb_kernel<<<1, 64, 0, s1>>>(b1, hb1);
    init_hb_kernel<<<1, 64, 0, s1>>>(b2, hb2);
    cudaEventRecord(e_hb, s1);
    zero_deg_kernel<<<nBlocks256, 256, 0, s1>>>(deg, N);
    hist_kernel<<<eBlocks256, 256, 0, s1>>>(dst, deg, E);
    scan1_kernel<<<scanBlocks, 256, 0, s1>>>(deg, off, bsum, N);
    scan2_kernel<<<1, 256, 0, s1>>>(bsum, bsumex, scanBlocks);
    scan3_kernel<<<nBlocks256, 256, 0, s1>>>(off, cur, bsumex, N);
    fill_kernel<<<eBlocks256, 256, 0, s1>>>(src, dst, ew, cur, edata, E);
    cudaEventRecord(e_csr, s1);

    // main stream: weight split then layer-1 dense work
    wsplit_kernel<<<(64 * 256 / 2 + 255) / 256, 256>>>(W1, whi1, wlo1, 64 * 256 / 2);
    wsplit_kernel<<<(64 * 64 / 2 + 255) / 256, 256>>>(W2, whi2, wlo2, 64 * 64 / 2);
    gemm_mma_kernel<0, 256><<<gemmBlocks, 256>>>(x, whi1, wlo1, g, xn, N);
    cudaStreamWaitEvent(0, e_hb, 0);
    kA_kernel<<<rowBlocks, 256>>>(g, xn, hb1, xt, N);

    cudaStreamWaitEvent(0, e_csr, 0);
    gather_kc_kernel<<<rowBlocks, 256>>>(xt, edata, off, deg, h1, xn, N);

    // ---- layer 2 ----
    gemm_mma_kernel<1, 64><<<gemmBlocks, 256>>>(h1, whi2, wlo2, g, nullptr, N);
    kA_kernel<<<rowBlocks, 256>>>(g, xn, hb2, xt, N);
    gather_kc_kernel<<<rowBlocks, 256>>>(xt, edata, off, deg, out, nullptr, N);

    cudaEventDestroy(e0);
    cudaEventDestroy(e_hb);
    cudaEventDestroy(e_csr);
    cudaStreamDestroy(s1);
}

// round 10
// speedup vs baseline: 1.2430x; 1.0012x over previous
#include <cuda_runtime.h>
#include <cuda_bf16.h>
#include <cuda_fp16.h>
#include <cstdint>

// ============================================================================
// HGCN (2-layer hyperbolic GCN), c = 1.
//
// R10 pipeline (= R9 + fp16 xt to halve gather L2 traffic):
//   main stream:  wsplit(W1) -> wsplit(W2) -> mmaGEMM<0>(x,W1) ->
//                 [join hb] kA1 -> [join csr] gather1 ->
//                 mmaGEMM<1>(h1,W2) -> kA2 -> gather2
//   side stream:  init_hb x2 -> zero_deg -> hist -> scan1..3 -> fill
//
// GEMM math: fp32 operands split a = hi + lo (bf16 each);
//   a*b ~= ah*bh + ah*bl + al*bh  (residual ~2^-16)
// xt stored as fp16 (single rounding, ~1.7e-4 RMS rel), accumulated in fp32.
// ============================================================================

#define BALL_MAXN 0.996f     // (1 - 4e-3)/sqrt(c)
#define EPSN      1e-15f
#define NODES_MAX 80000
#define E_MAX     1300000
#define DIM       64

__device__ float  d_g  [NODES_MAX * DIM];
__device__ __half d_xt [NODES_MAX * DIM];
__device__ float  d_h1 [NODES_MAX * DIM];
__device__ float  d_xn [NODES_MAX];
__device__ float  d_hb1[65];
__device__ float  d_hb2[65];
__device__ int    d_deg[NODES_MAX];
__device__ int    d_off[NODES_MAX];
__device__ int    d_cur[NODES_MAX];
__device__ int    d_bsum[256];
__device__ int    d_bsumex[256];
__device__ int2   d_edata[E_MAX];
__device__ unsigned d_whi1[64 * 256 / 2];
__device__ unsigned d_wlo1[64 * 256 / 2];
__device__ unsigned d_whi2[64 * 64 / 2];
__device__ unsigned d_wlo2[64 * 64 / 2];

__device__ __forceinline__ float wsum(float v) {
#pragma unroll
    for (int o = 16; o; o >>= 1) v += __shfl_xor_sync(0xffffffffu, v, o);
    return v;
}

__device__ __forceinline__ float artanh_f(float x) {
    x = fminf(fmaxf(x, -1.0f + 1e-7f), 1.0f - 1e-7f);
    return 0.5f * logf((1.0f + x) / (1.0f - x));
}

// split a pair of fp32 into packed bf16x2 (hi) and bf16x2 (lo residual).
__device__ __forceinline__ void split2(float f0, float f1,
                                       unsigned& hi, unsigned& lo) {
    asm("cvt.rn.bf16x2.f32 %0, %1, %2;" : "=r"(hi) : "f"(f1), "f"(f0));
    float h0 = __uint_as_float(hi << 16);
    float h1 = __uint_as_float(hi & 0xffff0000u);
    float l0 = f0 - h0;
    float l1 = f1 - h1;
    asm("cvt.rn.bf16x2.f32 %0, %1, %2;" : "=r"(lo) : "f"(l1), "f"(l0));
}

#define MMA_BF16(d, a0, a1, a2, a3, b0, b1) \
    asm volatile("mma.sync.aligned.m16n8k16.row.col.f32.bf16.bf16.f32 " \
        "{%0,%1,%2,%3}, {%4,%5,%6,%7}, {%8,%9}, {%0,%1,%2,%3};" \
        : "+f"((d)[0]), "+f"((d)[1]), "+f"((d)[2]), "+f"((d)[3]) \
        : "r"(a0), "r"(a1), "r"(a2), "r"(a3), "r"(b0), "r"(b1))

// ---------------------------------------------------------------------------
// W split: fp32 [rows,K] -> packed bf16x2 hi/lo arrays (pairs along K).
// ---------------------------------------------------------------------------
__global__ void wsplit_kernel(const float* __restrict__ W,
                              unsigned* __restrict__ whi,
                              unsigned* __restrict__ wlo, int npairs) {
    int i = blockIdx.x * blockDim.x + threadIdx.x;
    if (i < npairs) {
        float2 f = ((const float2*)W)[i];
        unsigned hi, lo;
        split2(f.x, f.y, hi, lo);
        whi[i] = hi;
        wlo[i] = lo;
    }
}

// ---------------------------------------------------------------------------
// hb = proj(expmap0(b)); hb[64] = ||hb||^2.  One block, 64 threads.
// ---------------------------------------------------------------------------
__global__ void init_hb_kernel(const float* __restrict__ b, float* __restrict__ hb) {
    __shared__ float sm[2];
    int t = threadIdx.x;
    float v = b[t];
    float ss = wsum(v * v);
    if ((t & 31) == 0) sm[t >> 5] = ss;
    __syncthreads();
    float tot = sm[0] + sm[1];
    __syncthreads();
    float nr = sqrtf(tot);
    float n  = fmaxf(nr, EPSN);
    float tn = tanhf(n);
    float e  = v * (tn / n);
    float en = fmaxf(tn * (nr / n), EPSN);
    float cf = (en > BALL_MAXN) ? (BALL_MAXN / en) : 1.0f;
    e *= cf;
    hb[t] = e;
    float ss2 = wsum(e * e);
    if ((t & 31) == 0) sm[t >> 5] = ss2;
    __syncthreads();
    if (t == 0) hb[64] = sm[0] + sm[1];
}

// ---------------------------------------------------------------------------
// CSR build
// ---------------------------------------------------------------------------
__global__ void zero_deg_kernel(int* __restrict__ deg, int N) {
    int i = blockIdx.x * blockDim.x + threadIdx.x;
    if (i < N) deg[i] = 0;
}

__global__ void hist_kernel(const int* __restrict__ dst, int* __restrict__ deg, int E) {
    int e = blockIdx.x * blockDim.x + threadIdx.x;
    if (e < E) atomicAdd(&deg[dst[e]], 1);
}

__global__ void scan1_kernel(const int* __restrict__ deg, int* __restrict__ off,
                             int* __restrict__ bsum, int N) {
    __shared__ int sh[256];
    int tid  = threadIdx.x;
    int base = blockIdx.x * 1024;
    int idx0 = base + tid * 4;
    int v[4];
#pragma unroll
    for (int j = 0; j < 4; j++) {
        int id = idx0 + j;
        v[j] = (id < N) ? deg[id] : 0;
    }
    int t = v[0] + v[1] + v[2] + v[3];
    sh[tid] = t;
    __syncthreads();
#pragma unroll
    for (int o = 1; o < 256; o <<= 1) {
        int u = (tid >= o) ? sh[tid - o] : 0;
        __syncthreads();
        sh[tid] += u;
        __syncthreads();
    }
    int excl = sh[tid] - t;
    int run = excl;
#pragma unroll
    for (int j = 0; j < 4; j++) {
        int id = idx0 + j;
        if (id < N) off[id] = run;
        run += v[j];
    }
    if (tid == 255) bsum[blockIdx.x] = sh[255];
}

__global__ void scan2_kernel(const int* __restrict__ bsum, int* __restrict__ bsumex, int B) {
    __shared__ int sh[256];
    int tid = threadIdx.x;
    int t = (tid < B) ? bsum[tid] : 0;
    sh[tid] = t;
    __syncthreads();
#pragma unroll
    for (int o = 1; o < 256; o <<= 1) {
        int u = (tid >= o) ? sh[tid - o] : 0;
        __syncthreads();
        sh[tid] += u;
        __syncthreads();
    }
    if (tid < B) bsumex[tid] = sh[tid] - t;
}

__global__ void scan3_kernel(int* __restrict__ off, int* __restrict__ cur,
                             const int* __restrict__ bsumex, int N) {
    int i = blockIdx.x * blockDim.x + threadIdx.x;
    if (i < N) {
        int v = off[i] + bsumex[i >> 10];
        off[i] = v;
        cur[i] = v;
    }
}

__global__ void fill_kernel(const int* __restrict__ src, const int* __restrict__ dst,
                            const float* __restrict__ w, int* __restrict__ cur,
                            int2* __restrict__ ed, int E) {
    int e = blockIdx.x * blockDim.x + threadIdx.x;
    if (e >= E) return;
    int d = dst[e];
    int pos = atomicAdd(&cur[d], 1);
    ed[pos] = make_int2(src[e], __float_as_int(w[e]));
}

// ---------------------------------------------------------------------------
// Tensor-core GEMM: C[N,64] = A[N,K] @ W[64,K]^T   (fp32 via bf16 split).
// Tile M=128, N=64, BK=32. 8 warps: warp grid 4(m) x 2(n); each warp 32x32.
// MODE 0: fused encode scale (h0 = s(||x||)*x folded into C) + xn out.
// ---------------------------------------------------------------------------
#define BM 128
#define KPAD 17   // 16 bf16x2 pairs per 32-wide k-slab + 1 pad

template <int MODE, int K>
__global__ __launch_bounds__(256, 2)
void gemm_mma_kernel(const float* __restrict__ A,
                     const unsigned* __restrict__ whi,
                     const unsigned* __restrict__ wlo,
                     float* __restrict__ C, float* __restrict__ xn_io, int N) {
    __shared__ unsigned Ahi[BM * KPAD];
    __shared__ unsigned Alo[BM * KPAD];
    __shared__ float sred[4 * 256];
    __shared__ float ssc[BM];

    int tid  = threadIdx.x;
    int lane = tid & 31;
    int wid  = tid >> 5;
    int warp_m = wid >> 1;        // 0..3  -> m offset warp_m*32
    int warp_n = wid & 1;         // 0..1  -> n offset warp_n*32
    int block_row = blockIdx.x * BM;

    int qrow = lane >> 2;         // 0..7
    int qcol = lane & 3;          // 0..3

    float acc[2][4][4];
#pragma unroll
    for (int mt = 0; mt < 2; mt++)
#pragma unroll
        for (int nt = 0; nt < 4; nt++)
#pragma unroll
            for (int r = 0; r < 4; r++) acc[mt][nt][r] = 0.0f;

    float ssl[4] = {0.f, 0.f, 0.f, 0.f};

    for (int k0 = 0; k0 < K; k0 += 32) {
#pragma unroll
        for (int i = 0; i < 4; i++) {
            int idx = tid + i * 256;
            int r   = idx >> 3;
            int kq  = (idx & 7) << 2;
            int gr  = block_row + r;
            if (gr >= N) gr = N - 1;
            float4 v = *(const float4*)(A + (size_t)gr * K + k0 + kq);
            unsigned h0, l0, h1, l1;
            split2(v.x, v.y, h0, l0);
            split2(v.z, v.w, h1, l1);
            Ahi[r * KPAD + (kq >> 1)]     = h0;
            Alo[r * KPAD + (kq >> 1)]     = l0;
            Ahi[r * KPAD + (kq >> 1) + 1] = h1;
            Alo[r * KPAD + (kq >> 1) + 1] = l1;
            if (MODE == 0)
                ssl[i] += v.x * v.x + v.y * v.y + v.z * v.z + v.w * v.w;
        }
        __syncthreads();

#pragma unroll
        for (int kc = 0; kc < 2; kc++) {
            int pc = kc * 8 + qcol;
            unsigned ah[2][4], al[2][4];
#pragma unroll
            for (int mt = 0; mt < 2; mt++) {
                int r0 = warp_m * 32 + mt * 16 + qrow;
                ah[mt][0] = Ahi[r0 * KPAD + pc];
                ah[mt][1] = Ahi[(r0 + 8) * KPAD + pc];
                ah[mt][2] = Ahi[r0 * KPAD + pc + 4];
                ah[mt][3] = Ahi[(r0 + 8) * KPAD + pc + 4];
                al[mt][0] = Alo[r0 * KPAD + pc];
                al[mt][1] = Alo[(r0 + 8) * KPAD + pc];
                al[mt][2] = Alo[r0 * KPAD + pc + 4];
                al[mt][3] = Alo[(r0 + 8) * KPAD + pc + 4];
            }
#pragma unroll
            for (int nt = 0; nt < 4; nt++) {
                int n  = warp_n * 32 + nt * 8 + qrow;
                int kp = (k0 + kc * 16) / 2 + qcol;
                int bidx = n * (K / 2) + kp;
                unsigned bh0 = __ldg(&whi[bidx]);
                unsigned bh1 = __ldg(&whi[bidx + 4]);
                unsigned bl0 = __ldg(&wlo[bidx]);
                unsigned bl1 = __ldg(&wlo[bidx + 4]);
#pragma unroll
                for (int mt = 0; mt < 2; mt++) {
                    MMA_BF16(acc[mt][nt], ah[mt][0], ah[mt][1], ah[mt][2], ah[mt][3], bh0, bh1);
                    MMA_BF16(acc[mt][nt], ah[mt][0], ah[mt][1], ah[mt][2], ah[mt][3], bl0, bl1);
                    MMA_BF16(acc[mt][nt], al[mt][0], al[mt][1], al[mt][2], al[mt][3], bh0, bh1);
                }
            }
        }
        __syncthreads();
    }

    if (MODE == 0) {
        sred[0 * 256 + tid] = ssl[0];
        sred[1 * 256 + tid] = ssl[1];
        sred[2 * 256 + tid] = ssl[2];
        sred[3 * 256 + tid] = ssl[3];
        __syncthreads();
        if (tid < 128) {
            int r   = tid;
            int grp = r >> 5;
            int t0  = (r & 31) << 3;
            float s2 = 0.0f;
#pragma unroll
            for (int j = 0; j < 8; j++) s2 += sred[grp * 256 + t0 + j];
            float nxr = sqrtf(s2);
            float nx  = fmaxf(nxr, EPSN);
            float t   = tanhf(nx);
            float en  = fmaxf(t * (nxr / nx), EPSN);
            float cf  = (en > BALL_MAXN) ? (BALL_MAXN / en) : 1.0f;
            ssc[r] = (t / nx) * cf;
            int gr = block_row + r;
            if (gr < N) xn_io[gr] = fmaxf(en * cf, EPSN);
        }
        __syncthreads();
    }

#pragma unroll
    for (int mt = 0; mt < 2; mt++) {
#pragma unroll
        for (int nt = 0; nt < 4; nt++) {
            int r0 = warp_m * 32 + mt * 16 + qrow;
            int c  = warp_n * 32 + nt * 8 + qcol * 2;
            int gr0 = block_row + r0;
            int gr1 = gr0 + 8;
            if (gr0 < N) {
                float sc = (MODE == 0) ? ssc[r0] : 1.0f;
                float2 o = make_float2(acc[mt][nt][0] * sc, acc[mt][nt][1] * sc);
                *(float2*)(C + (size_t)gr0 * DIM + c) = o;
            }
            if (gr1 < N) {
                float sc = (MODE == 0) ? ssc[r0 + 8] : 1.0f;
                float2 o = make_float2(acc[mt][nt][2] * sc, acc[mt][nt][3] * sc);
                *(float2*)(C + (size_t)gr1 * DIM + c) = o;
            }
        }
    }
}

// ---------------------------------------------------------------------------
// kA: mv = proj(mobius_matvec tail); h = proj(mobius_add(mv, hb)); xt = logmap0.
// Warp per row, 2 dims per lane. Output stored fp16 (math all fp32).
// ---------------------------------------------------------------------------
__global__ void kA_kernel(const float* __restrict__ g,
                          const float* __restrict__ xnarr,
                          const float* __restrict__ hb,
                          __half* __restrict__ xt_out, int N) {
    int row  = blockIdx.x * 8 + (threadIdx.x >> 5);
    int lane = threadIdx.x & 31;
    if (row >= N) return;

    float2 mx = *(const float2*)(g + (size_t)row * DIM + lane * 2);
    float xn = xnarr[row];

    float mxn2 = wsum(mx.x * mx.x + mx.y * mx.y);
    float mxnr = sqrtf(mxn2);
    float mxn  = fmaxf(mxnr, EPSN);
    float tv   = tanhf(mxn / xn * artanh_f(xn));
    float rs   = tv / mxn;
    float rx = mx.x * rs, ry = mx.y * rs;

    float rn = fmaxf(mxnr * fabsf(rs), EPSN);
    if (rn > BALL_MAXN) { float f = BALL_MAXN / rn; rx *= f; ry *= f; }

    float hbx = hb[lane * 2], hby = hb[lane * 2 + 1];
    float y2  = hb[64];
    float x2  = wsum(rx * rx + ry * ry);
    float xy  = wsum(rx * hbx + ry * hby);
    float den = fmaxf(1.0f + 2.0f * xy + x2 * y2, EPSN);
    float ca  = (1.0f + 2.0f * xy + y2) / den;
    float cb  = (1.0f - x2) / den;
    float hx = ca * rx + cb * hbx;
    float hy = ca * ry + cb * hby;

    float hn2 = wsum(hx * hx + hy * hy);
    float hnr = sqrtf(hn2);
    float hn  = fmaxf(hnr, EPSN);
    float cf2 = (hn > BALL_MAXN) ? (BALL_MAXN / hn) : 1.0f;
    hx *= cf2; hy *= cf2;

    float hna = fmaxf(hnr * cf2, EPSN);
    float lc  = artanh_f(hna) / hna;
    __half2 o = __floats2half2_rn(hx * lc, hy * lc);
    *(__half2*)(xt_out + (size_t)row * DIM + lane * 2) = o;
}

// ---------------------------------------------------------------------------
// Gather + kC: agg = sum_e w*xt[src] over CSR list of this dst node, then
// h = proj(expmap0(agg)); xt = relu(logmap0(h)); out = proj(expmap0(xt)).
// Warp per node, 2 dims per lane. xt is fp16; accumulation fp32.
// ---------------------------------------------------------------------------
__global__ void gather_kc_kernel(const __half* __restrict__ xt,
                                 const int2* __restrict__ ed,
                                 const int* __restrict__ off,
                                 const int* __restrict__ deg,
                                 float* __restrict__ out,
                                 float* __restrict__ xn_out, int N) {
    int row  = blockIdx.x * 8 + (threadIdx.x >> 5);
    int lane = threadIdx.x & 31;
    if (row >= N) return;

    int beg = off[row];
    int dc  = deg[row];

    float ax = 0.0f, ay = 0.0f;
    for (int i0 = 0; i0 < dc; i0 += 32) {
        int i = i0 + lane;
        int2 e = (i < dc) ? __ldg(&ed[beg + i]) : make_int2(0, 0);
        int cnt = min(32, dc - i0);
        for (int j = 0; j < cnt; j++) {
            int   s  = __shfl_sync(0xffffffffu, e.x, j);
            float wt = __int_as_float(__shfl_sync(0xffffffffu, e.y, j));
            __half2 v = *(const __half2*)(xt + (size_t)s * DIM + lane * 2);
            float2 f = __half22float2(v);
            ax = fmaf(wt, f.x, ax);
            ay = fmaf(wt, f.y, ay);
        }
    }

    float na2 = wsum(ax * ax + ay * ay);
    float nar = sqrtf(na2);
    float na  = fmaxf(nar, EPSN);
    float t   = tanhf(na);
    float f1  = t / na;
    float en  = fmaxf(t * (nar / na), EPSN);
    float c1  = (en > BALL_MAXN) ? (BALL_MAXN / en) : 1.0f;
    float hn  = fmaxf(en * c1, EPSN);
    float lco = artanh_f(hn) / hn * (f1 * c1);

    float lx = fmaxf(ax * lco, 0.0f);
    float ly = fmaxf(ay * lco, 0.0f);

    float nx2 = wsum(lx * lx + ly * ly);
    float nxr = sqrtf(nx2);
    float nx  = fmaxf(nxr, EPSN);
    float t2  = tanhf(nx);
    float f2  = t2 / nx;
    float en2 = fmaxf(t2 * (nxr / nx), EPSN);
    float c2  = (en2 > BALL_MAXN) ? (BALL_MAXN / en2) : 1.0f;

    float2 o = make_float2(lx * (f2 * c2), ly * (f2 * c2));
    *(float2*)(out + (size_t)row * DIM + lane * 2) = o;

    if (xn_out != nullptr && lane == 0)
        xn_out[row] = fmaxf(en2 * c2, EPSN);
}

// ---------------------------------------------------------------------------
// Launch: CSR build + hb init on side stream, hidden under W split + GEMM1.
// ---------------------------------------------------------------------------
extern "C" void kernel_launch(void* const* d_in, const int* in_sizes, int n_in,
                              void* d_out, int out_size) {
    const float* x   = (const float*)d_in[0];
    const int*   src = (const int*)  d_in[1];
    const int*   dst = (const int*)  d_in[2];
    const float* ew  = (const float*)d_in[3];
    const float* W1  = (const float*)d_in[4];
    const float* b1  = (const float*)d_in[5];
    const float* W2  = (const float*)d_in[6];
    const float* b2  = (const float*)d_in[7];
    float* out = (float*)d_out;

    int N = in_sizes[0] / 256;
    int E = in_sizes[1];

    float *g, *h1, *xn, *hb1, *hb2;
    __half* xt;
    int *deg, *off, *cur, *bsum, *bsumex;
    int2* edata;
    unsigned *whi1, *wlo1, *whi2, *wlo2;
    cudaGetSymbolAddress((void**)&g,      d_g);
    cudaGetSymbolAddress((void**)&xt,     d_xt);
    cudaGetSymbolAddress((void**)&h1,     d_h1);
    cudaGetSymbolAddress((void**)&xn,     d_xn);
    cudaGetSymbolAddress((void**)&hb1,    d_hb1);
    cudaGetSymbolAddress((void**)&hb2,    d_hb2);
    cudaGetSymbolAddress((void**)&deg,    d_deg);
    cudaGetSymbolAddress((void**)&off,    d_off);
    cudaGetSymbolAddress((void**)&cur,    d_cur);
    cudaGetSymbolAddress((void**)&bsum,   d_bsum);
    cudaGetSymbolAddress((void**)&bsumex, d_bsumex);
    cudaGetSymbolAddress((void**)&edata,  d_edata);
    cudaGetSymbolAddress((void**)&whi1,   d_whi1);
    cudaGetSymbolAddress((void**)&wlo1,   d_wlo1);
    cudaGetSymbolAddress((void**)&whi2,   d_whi2);
    cudaGetSymbolAddress((void**)&wlo2,   d_wlo2);

    int rowBlocks  = (N + 7) / 8;
    int gemmBlocks = (N + BM - 1) / BM;
    int nBlocks256 = (N + 255) / 256;
    int eBlocks256 = (E + 255) / 256;
    int scanBlocks = (N + 1023) / 1024;

    cudaStream_t s1;
    cudaStreamCreateWithFlags(&s1, cudaStreamNonBlocking);
    cudaEvent_t e0, e_hb, e_csr;
    cudaEventCreateWithFlags(&e0,    cudaEventDisableTiming);
    cudaEventCreateWithFlags(&e_hb,  cudaEventDisableTiming);
    cudaEventCreateWithFlags(&e_csr, cudaEventDisableTiming);

    // fork
    cudaEventRecord(e0, 0);
    cudaStreamWaitEvent(s1, e0, 0);

    // side stream: hb constants, then CSR build
    init_hb_kernel<<<1, 64, 0, s1>>>(b1, hb1);
    init_hb_kernel<<<1, 64, 0, s1>>>(b2, hb2);
    cudaEventRecord(e_hb, s1);
    zero_deg_kernel<<<nBlocks256, 256, 0, s1>>>(deg, N);
    hist_kernel<<<eBlocks256, 256, 0, s1>>>(dst, deg, E);
    scan1_kernel<<<scanBlocks, 256, 0, s1>>>(deg, off, bsum, N);
    scan2_kernel<<<1, 256, 0, s1>>>(bsum, bsumex, scanBlocks);
    scan3_kernel<<<nBlocks256, 256, 0, s1>>>(off, cur, bsumex, N);
    fill_kernel<<<eBlocks256, 256, 0, s1>>>(src, dst, ew, cur, edata, E);
    cudaEventRecord(e_csr, s1);

    // main stream: weight split then layer-1 dense work
    wsplit_kernel<<<(64 * 256 / 2 + 255) / 256, 256>>>(W1, whi1, wlo1, 64 * 256 / 2);
    wsplit_kernel<<<(64 * 64 / 2 + 255) / 256, 256>>>(W2, whi2, wlo2, 64 * 64 / 2);
    gemm_mma_kernel<0, 256><<<gemmBlocks, 256>>>(x, whi1, wlo1, g, xn, N);
    cudaStreamWaitEvent(0, e_hb, 0);
    kA_kernel<<<rowBlocks, 256>>>(g, xn, hb1, xt, N);

    cudaStreamWaitEvent(0, e_csr, 0);
    gather_kc_kernel<<<rowBlocks, 256>>>(xt, edata, off, deg, h1, xn, N);

    // ---- layer 2 ----
    gemm_mma_kernel<1, 64><<<gemmBlocks, 256>>>(h1, whi2, wlo2, g, nullptr, N);
    kA_kernel<<<rowBlocks, 256>>>(g, xn, hb2, xt, N);
    gather_kc_kernel<<<rowBlocks, 256>>>(xt, edata, off, deg, out, nullptr, N);

    cudaEventDestroy(e0);
    cudaEventDestroy(e_hb);
    cudaEventDestroy(e_csr);
    cudaStreamDestroy(s1);
}